// round 8
// baseline (speedup 1.0000x reference)
#include <cuda_runtime.h>
#include <cuda_bf16.h>
#include <cstdint>

// ---------------- problem constants ----------------
#define Dm 256
#define Hh 8
#define HD 32
#define Ll 4
#define Pp 4
#define Bb 32
#define NQ 100
#define Nn (Bb*NQ)          // 3200
#define T_TOTAL 3840
#define LP 16
#define HLP 128

// ---------------- device scratch ----------------
__device__ float g_value[(size_t)Bb * T_TOTAL * Dm];   // ~126MB
__device__ float g_off[Nn * HLP];
__device__ float g_awl[Nn * HLP];
__device__ float g_hsproj[Nn * Dm];
__device__ float g_attnres[Nn * Dm];
__device__ float g_gates[Nn * 4 * Dm];
__device__ __nv_bfloat16 g_Bh[Dm * Dm];        // W_value^T [n][k]
__device__ __nv_bfloat16 g_Bl[Dm * Dm];
__device__ __nv_bfloat16 g_Gh[1024 * 1024];    // [Wih|Whh] [j][k]
__device__ __nv_bfloat16 g_Gl[1024 * 1024];
__device__ __nv_bfloat16 g_Ch[256 * 32];       // Wctx^T [e][d]
__device__ __nv_bfloat16 g_Cl[256 * 32];
__device__ __nv_bfloat16 g_Ph[512 * 512];      // proj B [n][k]
__device__ __nv_bfloat16 g_Pl[512 * 512];

__device__ __forceinline__ float tanh_fast(float x) {
    float e = __expf(2.0f * x);
    return 1.0f - 2.0f / (e + 1.0f);
}
__device__ __forceinline__ float tanha(float x) {
    float y;
    asm("tanh.approx.f32 %0, %1;" : "=f"(y) : "f"(x));
    return y;
}
__device__ __forceinline__ float sigm(float x) {
    return 1.0f / (1.0f + __expf(-x));
}
__device__ __forceinline__ uint32_t smem_u32(const void* p) {
    uint32_t a;
    asm("{ .reg .u64 t; cvta.to.shared.u64 t, %1; cvt.u32.u64 %0, t; }"
        : "=r"(a) : "l"(p));
    return a;
}
__device__ __forceinline__ void bf16_split(float x, __nv_bfloat16& h, __nv_bfloat16& l) {
    h = __float2bfloat16_rn(x);
    l = __float2bfloat16_rn(x - __bfloat162float(h));
}

// ---------------- cp.async ----------------
__device__ __forceinline__ void cp_async16(uint32_t dst, const void* src) {
    asm volatile("cp.async.cg.shared.global [%0], [%1], 16;"
                 :: "r"(dst), "l"(src) : "memory");
}
#define CP_COMMIT() asm volatile("cp.async.commit_group;" ::: "memory")
#define CP_WAIT0()  asm volatile("cp.async.wait_group 0;" ::: "memory")

// ---------------- mma.sync / ldmatrix ----------------
__device__ __forceinline__ void ldm_x4(uint32_t* r, uint32_t addr) {
    asm volatile("ldmatrix.sync.aligned.m8n8.x4.shared.b16 {%0,%1,%2,%3}, [%4];"
        : "=r"(r[0]), "=r"(r[1]), "=r"(r[2]), "=r"(r[3]) : "r"(addr));
}
#define MMA16816(d, a, b) \
    asm volatile("mma.sync.aligned.m16n8k16.row.col.f32.bf16.bf16.f32 " \
        "{%0,%1,%2,%3}, {%4,%5,%6,%7}, {%8,%9}, {%0,%1,%2,%3};" \
        : "+f"((d)[0]), "+f"((d)[1]), "+f"((d)[2]), "+f"((d)[3]) \
        : "r"((a)[0]), "r"((a)[1]), "r"((a)[2]), "r"((a)[3]), \
          "r"((b)[0]), "r"((b)[1]))

// 3-term fused chunk (used by proj/gates/sample kernels)
template<int NT2, int KS>
__device__ __forceinline__ void mma_chunk_t(
    uint32_t aH, uint32_t aL, uint32_t bH, uint32_t bL,
    uint32_t stride2, int wm, int wn, int lane, float* acc)
{
    int arow = lane & 15, acol8 = (lane >> 4) * 8;
    int brow = ((lane >> 4) & 1) * 8 + (lane & 7);
    int bcol8 = ((lane >> 3) & 1) * 8;
#pragma unroll
    for (int ks = 0; ks < KS; ks++) {
        uint32_t Ah[2][4], Al[2][4], Bh[NT2][4], Bl[NT2][4];
#pragma unroll
        for (int mt = 0; mt < 2; mt++) {
            uint32_t off = (uint32_t)(wm + mt * 16 + arow) * stride2
                         + (uint32_t)(ks * 16 + acol8) * 2;
            ldm_x4(Ah[mt], aH + off);
            ldm_x4(Al[mt], aL + off);
        }
#pragma unroll
        for (int nt2 = 0; nt2 < NT2; nt2++) {
            uint32_t off = (uint32_t)(wn + nt2 * 16 + brow) * stride2
                         + (uint32_t)(ks * 16 + bcol8) * 2;
            ldm_x4(Bh[nt2], bH + off);
            ldm_x4(Bl[nt2], bL + off);
        }
#pragma unroll
        for (int mt = 0; mt < 2; mt++)
#pragma unroll
            for (int nt = 0; nt < 2 * NT2; nt++) {
                float* a4 = acc + (mt * 2 * NT2 + nt) * 4;
                uint32_t* bh = &Bh[nt >> 1][(nt & 1) * 2];
                uint32_t* bl = &Bl[nt >> 1][(nt & 1) * 2];
                MMA16816(a4, Ah[mt], bh);
                MMA16816(a4, Al[mt], bh);
                MMA16816(a4, Ah[mt], bl);
            }
    }
}

// single-B-piece chunk: NTERM=2 -> (Ah+Al)xB ; NTERM=1 -> AhxB
template<int NT2, int KS, int NTERM>
__device__ __forceinline__ void mma_piece_t(
    uint32_t aH, uint32_t aL, uint32_t bP,
    uint32_t stride2, int wm, int wn, int lane, float* acc)
{
    int arow = lane & 15, acol8 = (lane >> 4) * 8;
    int brow = ((lane >> 4) & 1) * 8 + (lane & 7);
    int bcol8 = ((lane >> 3) & 1) * 8;
#pragma unroll
    for (int ks = 0; ks < KS; ks++) {
        uint32_t Ah[2][4], Al[2][4], B[NT2][4];
#pragma unroll
        for (int mt = 0; mt < 2; mt++) {
            uint32_t off = (uint32_t)(wm + mt * 16 + arow) * stride2
                         + (uint32_t)(ks * 16 + acol8) * 2;
            ldm_x4(Ah[mt], aH + off);
            if (NTERM == 2) ldm_x4(Al[mt], aL + off);
        }
#pragma unroll
        for (int nt2 = 0; nt2 < NT2; nt2++) {
            uint32_t off = (uint32_t)(wn + nt2 * 16 + brow) * stride2
                         + (uint32_t)(ks * 16 + bcol8) * 2;
            ldm_x4(B[nt2], bP + off);
        }
#pragma unroll
        for (int mt = 0; mt < 2; mt++)
#pragma unroll
            for (int nt = 0; nt < 2 * NT2; nt++) {
                float* a4 = acc + (mt * 2 * NT2 + nt) * 4;
                uint32_t* b2 = &B[nt >> 1][(nt & 1) * 2];
                MMA16816(a4, Ah[mt], b2);
                if (NTERM == 2) MMA16816(a4, Al[mt], b2);
            }
    }
}

#define STR 72
#define OFF_AH 0
#define OFF_AL 9216
#define OFF_BH 18432
#define OFF_BL 36864
#define GEMM_SMEM 55296
// pipelined value layout: A double buf (h+l), B piece double buf
#define PV_AH(b) ((b) * 18432)
#define PV_AL(b) ((b) * 18432 + 9216)
#define PV_P(b)  (36864 + (b) * 36864)
#define VP_SMEM  110592

// =====================================================================
// K0a: prep W_value split only
// =====================================================================
__global__ __launch_bounds__(256) void k_prep_B(const float* __restrict__ Wvalue)
{
    int idx = blockIdx.x * 256 + threadIdx.x;   // < 65536
    int n = idx >> 8, k = idx & 255;
    __nv_bfloat16 h, l;
    bf16_split(Wvalue[k * Dm + n], h, l);
    g_Bh[idx] = h; g_Bl[idx] = l;
}

// =====================================================================
// K0b: prep remaining weights
// =====================================================================
__global__ __launch_bounds__(256) void k_prep_rest(
    const float* __restrict__ Wih, const float* __restrict__ Whh,
    const float* __restrict__ Wctx,
    const float* __restrict__ Woff, const float* __restrict__ Waw,
    const float* __restrict__ Whs)
{
    int idx = blockIdx.x * 256 + threadIdx.x;
    __nv_bfloat16 h, l;
    if (idx < 1048576) {
        int j = idx >> 10, k = idx & 1023;
        float v = (k < 768) ? Wih[(size_t)j * 768 + k]
                            : Whh[(size_t)j * 256 + (k - 768)];
        bf16_split(v, h, l);
        g_Gh[idx] = h; g_Gl[idx] = l;
    } else if (idx < 1048576 + 8192) {
        int i = idx - 1048576;
        int e = i >> 5, k = i & 31;
        bf16_split(Wctx[k * 256 + e], h, l);
        g_Ch[i] = h; g_Cl[i] = l;
    } else if (idx < 1056768 + 262144) {
        int i = idx - 1056768;
        int n = i >> 9, k = i & 511;
        float v;
        if (n < 128)      v = Woff[k * 128 + n];
        else if (n < 256) v = Waw[k * 128 + (n - 128)];
        else              v = (k < 256) ? Whs[k * 256 + (n - 256)] : 0.f;
        bf16_split(v, h, l);
        g_Ph[i] = h; g_Pl[i] = l;
    }
}

// =====================================================================
// K1: correctly pipelined value GEMM. M=122880, N=256, K=256. grid 1920.
// 8 sub-iters (4 chunks x {Bh, Bl}); cp.async issued ONLY after the
// barrier that proves the target buffer's last reader finished.
// =====================================================================
__global__ __launch_bounds__(256, 2) void k_value_mma(
    const float* __restrict__ A, const float* __restrict__ bias)
{
    extern __shared__ char smem[];
    uint32_t sb = smem_u32(smem);
    int tid = threadIdx.x;
    int w = tid >> 5, lane = tid & 31;
    int wm = (w >> 2) * 32, wn = (w & 3) * 64;
    int row0 = blockIdx.x * 64;

    float acc[64];
#pragma unroll
    for (int i = 0; i < 64; i++) acc[i] = 0.f;

    uint4 pfH[2], pfL[2];

    // LDG + split A chunk c into registers
    auto ldA = [&](int c) {
#pragma unroll
        for (int i = 0; i < 2; i++) {
            int g = tid + i * 256;
            int m = g >> 3, kg = g & 7;
            const float* s = A + (size_t)(row0 + m) * Dm + c * 64 + kg * 8;
            float4 v0 = *(const float4*)s;
            float4 v1 = *(const float4*)(s + 4);
            float xs[8] = {v0.x, v0.y, v0.z, v0.w, v1.x, v1.y, v1.z, v1.w};
            __nv_bfloat16 hh[8], ll[8];
#pragma unroll
            for (int j = 0; j < 8; j++) bf16_split(xs[j], hh[j], ll[j]);
            pfH[i] = *(uint4*)hh;
            pfL[i] = *(uint4*)ll;
        }
    };
    auto stsA = [&](int buf) {
        __nv_bfloat16* ah = (__nv_bfloat16*)(smem + PV_AH(buf));
        __nv_bfloat16* al = (__nv_bfloat16*)(smem + PV_AL(buf));
#pragma unroll
        for (int i = 0; i < 2; i++) {
            int g = tid + i * 256;
            int m = g >> 3, kg = g & 7;
            *(uint4*)&ah[m * STR + kg * 8] = pfH[i];
            *(uint4*)&al[m * STR + kg * 8] = pfL[i];
        }
    };
    // cp.async one B piece (h or l) of chunk c into buffer buf
    auto cpB = [&](int c, int piece, int buf) {
        const __nv_bfloat16* src = piece ? g_Bl : g_Bh;
        uint32_t dst = sb + PV_P(buf);
#pragma unroll
        for (int i = 0; i < 8; i++) {
            int g = tid + i * 256;          // 2048 groups of 16B
            int r = g >> 3, kg = g & 7;
            cp_async16(dst + (uint32_t)(r * STR + kg * 8) * 2,
                       &src[r * Dm + c * 64 + kg * 8]);
        }
    };

    // prologue: A chunk 0 staged, B piece 0 (Bh[0]) in flight
    ldA(0);
    stsA(0);
    cpB(0, 0, 0);
    CP_COMMIT();

    for (int t = 0; t < 8; t++) {
        int c = t >> 1, piece = t & 1;
        // early LDG for next A chunk (global read — no smem hazard)
        if (piece == 0 && c < 3) ldA(c + 1);
        CP_WAIT0();                 // piece t's copy complete (this thread)
        __syncthreads();            // all threads: piece t visible; iter t-1 reads done
        // safe now: bufP[(t+1)&1] was last read at iter t-1
        if (t + 1 < 8) { cpB((t + 1) >> 1, (t + 1) & 1, (t + 1) & 1); CP_COMMIT(); }
        // safe now: bufA[(c+1)&1] was last read at chunk c-1 (iter <= 2c-1)
        if (piece == 1 && c < 3) stsA((c + 1) & 1);
        if (piece == 0)
            mma_piece_t<4, 4, 2>(sb + PV_AH(c & 1), sb + PV_AL(c & 1),
                                 sb + PV_P(t & 1), STR * 2, wm, wn, lane, acc);
        else
            mma_piece_t<4, 4, 1>(sb + PV_AH(c & 1), sb + PV_AL(c & 1),
                                 sb + PV_P(t & 1), STR * 2, wm, wn, lane, acc);
    }

#pragma unroll
    for (int mt = 0; mt < 2; mt++)
#pragma unroll
        for (int nt = 0; nt < 8; nt++) {
            float* a4 = &acc[(mt * 8 + nt) * 4];
            int r = row0 + wm + mt * 16 + (lane >> 2);
            int cg = wn + nt * 8 + (lane & 3) * 2;
            float b0 = __ldg(&bias[cg]), b1 = __ldg(&bias[cg + 1]);
            *(float2*)&g_value[(size_t)r * Dm + cg] =
                make_float2(a4[0] + b0, a4[1] + b1);
            *(float2*)&g_value[(size_t)(r + 8) * Dm + cg] =
                make_float2(a4[2] + b0, a4[3] + b1);
        }
}

// =====================================================================
// K2: proj GEMM. [h0|query](3200x512) @ g_P(512x512). grid (4,50)
// =====================================================================
__global__ __launch_bounds__(256) void k_proj_mma(
    const float* __restrict__ h0, const float* __restrict__ query,
    const float* __restrict__ boff, const float* __restrict__ baw,
    const float* __restrict__ bhs,  const float* __restrict__ bctx)
{
    extern __shared__ char smem[];
    uint32_t sb = smem_u32(smem);
    int tid = threadIdx.x;
    int w = tid >> 5, lane = tid & 31;
    int wm = (w >> 2) * 32, wn = (w & 3) * 32;
    int row0 = blockIdx.y * 64;
    int col0 = blockIdx.x * 128;

    float acc[32];
#pragma unroll
    for (int i = 0; i < 32; i++) acc[i] = 0.f;

    __nv_bfloat16* sAh = (__nv_bfloat16*)(smem + OFF_AH);
    __nv_bfloat16* sAl = (__nv_bfloat16*)(smem + OFF_AL);
    __nv_bfloat16* sBh = (__nv_bfloat16*)(smem + OFF_BH);
    __nv_bfloat16* sBl = (__nv_bfloat16*)(smem + OFF_BL);

    for (int c = 0; c < 8; c++) {
        const float* src = (c < 4) ? h0 : query;
        int kkb = (c & 3) * 64;
        for (int g = tid; g < 512; g += 256) {
            int m = g >> 3, kg = g & 7;
            const float* s = src + (size_t)(row0 + m) * Dm + kkb + kg * 8;
            float4 v0 = *(const float4*)s;
            float4 v1 = *(const float4*)(s + 4);
            float xs[8] = {v0.x, v0.y, v0.z, v0.w, v1.x, v1.y, v1.z, v1.w};
            __nv_bfloat16 hh[8], ll[8];
#pragma unroll
            for (int i = 0; i < 8; i++) bf16_split(xs[i], hh[i], ll[i]);
            *(uint4*)&sAh[m * STR + kg * 8] = *(uint4*)hh;
            *(uint4*)&sAl[m * STR + kg * 8] = *(uint4*)ll;
        }
        for (int g = tid; g < 1024; g += 256) {
            int n = g >> 3, kg = g & 7;
            int gi = (col0 + n) * 512 + c * 64 + kg * 8;
            *(uint4*)&sBh[n * STR + kg * 8] = *(const uint4*)&g_Ph[gi];
            *(uint4*)&sBl[n * STR + kg * 8] = *(const uint4*)&g_Pl[gi];
        }
        __syncthreads();
        mma_chunk_t<2, 4>(sb + OFF_AH, sb + OFF_AL, sb + OFF_BH, sb + OFF_BL,
                          STR * 2, wm, wn, lane, acc);
        __syncthreads();
    }

    int bx = blockIdx.x;
#pragma unroll
    for (int mt = 0; mt < 2; mt++)
#pragma unroll
        for (int nt = 0; nt < 4; nt++) {
            float* a4 = &acc[(mt * 4 + nt) * 4];
            int r = row0 + wm + mt * 16 + (lane >> 2);
            int cl = wn + nt * 8 + (lane & 3) * 2;
            if (bx == 0) {
                float b0 = __ldg(&boff[cl]), b1 = __ldg(&boff[cl + 1]);
                *(float2*)&g_off[r * 128 + cl] = make_float2(a4[0] + b0, a4[1] + b1);
                *(float2*)&g_off[(r + 8) * 128 + cl] = make_float2(a4[2] + b0, a4[3] + b1);
            } else if (bx == 1) {
                float b0 = __ldg(&baw[cl]), b1 = __ldg(&baw[cl + 1]);
                *(float2*)&g_awl[r * 128 + cl] = make_float2(a4[0] + b0, a4[1] + b1);
                *(float2*)&g_awl[(r + 8) * 128 + cl] = make_float2(a4[2] + b0, a4[3] + b1);
            } else {
                int col = (bx - 2) * 128 + cl;
                float b0 = __ldg(&bhs[col]) + __ldg(&bctx[col]);
                float b1 = __ldg(&bhs[col + 1]) + __ldg(&bctx[col + 1]);
                *(float2*)&g_hsproj[r * 256 + col] = make_float2(a4[0] + b0, a4[1] + b1);
                *(float2*)&g_hsproj[(r + 8) * 256 + col] = make_float2(a4[2] + b0, a4[3] + b1);
            }
        }
}

// =====================================================================
// K3: sample + additive attention
// =====================================================================
#define A3STR 40
#define S3_AH  0
#define S3_AL  10240
#define S3_BH  20480
#define S3_BL  40960
#define S3_ADD 61440
#define S3_WA  62464
#define S3_AW  63488
#define S3_SC  64000
#define S3_SMEM 64512

__global__ __launch_bounds__(256) void k_sample_attn(
    const float* __restrict__ rp,
    const float* __restrict__ Walpha)
{
    extern __shared__ char sm3[];
    __nv_bfloat16* sAh3 = (__nv_bfloat16*)(sm3 + S3_AH);
    __nv_bfloat16* sAl3 = (__nv_bfloat16*)(sm3 + S3_AL);
    __nv_bfloat16* sBh3 = (__nv_bfloat16*)(sm3 + S3_BH);
    __nv_bfloat16* sBl3 = (__nv_bfloat16*)(sm3 + S3_BL);
    float* add_s = (float*)(sm3 + S3_ADD);
    float* Wa_s  = (float*)(sm3 + S3_WA);
    float* aw_s  = (float*)(sm3 + S3_AW);
    float* sc_s  = (float*)(sm3 + S3_SC);

    int n = blockIdx.x;
    int tid = threadIdx.x;
    int w = tid >> 5, lane = tid & 31;
    int b = n / NQ;

    for (int g = tid; g < 1024; g += 256) {
        int r = g >> 2, kg = (g & 3) * 8;
        *(uint4*)&sBh3[r * A3STR + kg] = *(const uint4*)&g_Ch[r * 32 + kg];
        *(uint4*)&sBl3[r * A3STR + kg] = *(const uint4*)&g_Cl[r * 32 + kg];
    }
    if (tid < 128) { aw_s[tid] = g_awl[n * 128 + tid]; sc_s[tid] = 0.f; }
    add_s[tid] = g_hsproj[n * 256 + tid];
    Wa_s[tid] = Walpha[tid];
    __syncthreads();

    if (lane < 16) {
        float v = aw_s[w * 16 + lane];
        float mx = v;
#pragma unroll
        for (int o = 8; o > 0; o >>= 1)
            mx = fmaxf(mx, __shfl_xor_sync(0x0000ffffu, mx, o, 16));
        float ev = __expf(v - mx);
        float s = ev;
#pragma unroll
        for (int o = 8; o > 0; o >>= 1)
            s += __shfl_xor_sync(0x0000ffffu, s, o, 16);
        aw_s[w * 16 + lane] = ev / s;
    }
    __syncthreads();

    {
        const int TLS[4]    = {2048, 1024, 512, 256};
        const int STARTS[4] = {0, 2048, 3072, 3584};
        int pair = tid >> 1, half = tid & 1;
        int h2 = pair >> 4, lp = pair & 15, l = lp >> 2;
        int Tl = TLS[l], st = STARTS[l];
        float ref = rp[n * Ll + l];
        float off = g_off[n * HLP + pair];
        float aw = aw_s[pair];
        float x = ref * (float)Tl + off - 0.5f;
        float xf = floorf(x);
        float w1 = x - xf, w0 = 1.0f - w1;
        int i0 = (int)xf, i1 = i0 + 1;
        float wa0 = aw * w0 * ((i0 >= 0 && i0 < Tl) ? 1.f : 0.f);
        float wa1 = aw * w1 * ((i1 >= 0 && i1 < Tl) ? 1.f : 0.f);
        int c0i = min(max(i0, 0), Tl - 1);
        int c1i = min(max(i1, 0), Tl - 1);
        size_t base0 = ((size_t)(b * T_TOTAL + st + c0i)) * Dm + h2 * HD + half * 16;
        size_t base1 = ((size_t)(b * T_TOTAL + st + c1i)) * Dm + h2 * HD + half * 16;
#pragma unroll
        for (int q4 = 0; q4 < 4; q4++) {
            float4 v0 = *(const float4*)&g_value[base0 + q4 * 4];
            float4 v1 = *(const float4*)&g_value[base1 + q4 * 4];
            float fx[4];
            fx[0] = wa0 * v0.x + wa1 * v1.x;
            fx[1] = wa0 * v0.y + wa1 * v1.y;
            fx[2] = wa0 * v0.z + wa1 * v1.z;
            fx[3] = wa0 * v0.w + wa1 * v1.w;
            __nv_bfloat16 hh[4], ll[4];
#pragma unroll
            for (int i = 0; i < 4; i++) bf16_split(fx[i], hh[i], ll[i]);
            int d = half * 16 + q4 * 4;
            *(uint2*)&sAh3[pair * A3STR + d] = *(uint2*)hh;
            *(uint2*)&sAl3[pair * A3STR + d] = *(uint2*)ll;
        }
    }
    __syncthreads();

    uint32_t aH = smem_u32(sAh3), aL = smem_u32(sAl3);
    uint32_t bH = smem_u32(sBh3), bL = smem_u32(sBl3);
    int wm = (w >> 1) * 32, wnl = (w & 1) * 32;
    float scoreacc[2][2] = {{0.f, 0.f}, {0.f, 0.f}};

#pragma unroll
    for (int pass = 0; pass < 4; pass++) {
        uint32_t boff2 = (uint32_t)(pass * 64 * A3STR * 2);
        float acc[32];
#pragma unroll
        for (int i = 0; i < 32; i++) acc[i] = 0.f;
        mma_chunk_t<2, 2>(aH, aL, bH + boff2, bL + boff2,
                          A3STR * 2, wm, wnl, lane, acc);
#pragma unroll
        for (int mt = 0; mt < 2; mt++)
#pragma unroll
            for (int nt = 0; nt < 4; nt++) {
                float* a4 = &acc[(mt * 4 + nt) * 4];
                int e0 = pass * 64 + wnl + nt * 8 + (lane & 3) * 2;
                scoreacc[mt][0] += tanha(a4[0] + add_s[e0]) * Wa_s[e0];
                scoreacc[mt][0] += tanha(a4[1] + add_s[e0 + 1]) * Wa_s[e0 + 1];
                scoreacc[mt][1] += tanha(a4[2] + add_s[e0]) * Wa_s[e0];
                scoreacc[mt][1] += tanha(a4[3] + add_s[e0 + 1]) * Wa_s[e0 + 1];
            }
    }

#pragma unroll
    for (int mt = 0; mt < 2; mt++) {
        float s0 = scoreacc[mt][0], s1 = scoreacc[mt][1];
        s0 += __shfl_xor_sync(0xffffffffu, s0, 1);
        s0 += __shfl_xor_sync(0xffffffffu, s0, 2);
        s1 += __shfl_xor_sync(0xffffffffu, s1, 1);
        s1 += __shfl_xor_sync(0xffffffffu, s1, 2);
        if ((lane & 3) == 0) {
            atomicAdd(&sc_s[wm + mt * 16 + (lane >> 2)], s0);
            atomicAdd(&sc_s[wm + mt * 16 + 8 + (lane >> 2)], s1);
        }
    }
    __syncthreads();

    if (lane < 16) {
        float v = sc_s[w * 16 + lane];
        float mx = v;
#pragma unroll
        for (int o = 8; o > 0; o >>= 1)
            mx = fmaxf(mx, __shfl_xor_sync(0x0000ffffu, mx, o, 16));
        float ev = __expf(v - mx);
        float s = ev;
#pragma unroll
        for (int o = 8; o > 0; o >>= 1)
            s += __shfl_xor_sync(0x0000ffffu, s, o, 16);
        sc_s[w * 16 + lane] = ev / s;
    }
    __syncwarp();

    {
        float accw = 0.f;
#pragma unroll
        for (int p = 0; p < 16; p++) {
            int r = (w * 16 + p) * A3STR + lane;
            accw += sc_s[w * 16 + p] *
                    (__bfloat162float(sAh3[r]) + __bfloat162float(sAl3[r]));
        }
        g_attnres[(size_t)n * Dm + w * HD + lane] = accw;
    }
}

// =====================================================================
// K4a/K4b: gates GEMMs
// =====================================================================
template<int NCHUNK, bool ACCUM>
__device__ __forceinline__ void gates_core(
    const float* token, const float* query, const float* h0, int tid)
{
    extern __shared__ char smem[];
    uint32_t sb = smem_u32(smem);
    int w = tid >> 5, lane = tid & 31;
    int wm = (w >> 2) * 32, wn = (w & 3) * 32;
    int row0 = blockIdx.y * 64;
    int col0 = blockIdx.x * 128;

    float acc[32];
#pragma unroll
    for (int i = 0; i < 32; i++) acc[i] = 0.f;

    __nv_bfloat16* sAh = (__nv_bfloat16*)(smem + OFF_AH);
    __nv_bfloat16* sAl = (__nv_bfloat16*)(smem + OFF_AL);
    __nv_bfloat16* sBh = (__nv_bfloat16*)(smem + OFF_BH);
    __nv_bfloat16* sBl = (__nv_bfloat16*)(smem + OFF_BL);

    const int segbase[3] = {0, 512, 768};
    for (int c = 0; c < NCHUNK; c++) {
        const float* src;
        int kcol;
        if (ACCUM) { src = g_attnres; kcol = 256 + c * 64; }
        else {
            int seg = c >> 2;
            src = (seg == 0) ? token : (seg == 1) ? query : h0;
            kcol = segbase[seg] + (c & 3) * 64;
        }
        int kkb = (c & 3) * 64;
        for (int g = tid; g < 512; g += 256) {
            int m = g >> 3, kg = g & 7;
            const float* s = src + (size_t)(row0 + m) * Dm + kkb + kg * 8;
            float4 v0 = *(const float4*)s;
            float4 v1 = *(const float4*)(s + 4);
            float xs[8] = {v0.x, v0.y, v0.z, v0.w, v1.x, v1.y, v1.z, v1.w};
            __nv_bfloat16 hh[8], ll[8];
#pragma unroll
            for (int i = 0; i < 8; i++) bf16_split(xs[i], hh[i], ll[i]);
            *(uint4*)&sAh[m * STR + kg * 8] = *(uint4*)hh;
            *(uint4*)&sAl[m * STR + kg * 8] = *(uint4*)ll;
        }
        for (int g = tid; g < 1024; g += 256) {
            int n = g >> 3, kg = g & 7;
            size_t gi = (size_t)(col0 + n) * 1024 + kcol + kg * 8;
            *(uint4*)&sBh[n * STR + kg * 8] = *(const uint4*)&g_Gh[gi];
            *(uint4*)&sBl[n * STR + kg * 8] = *(const uint4*)&g_Gl[gi];
        }
        __syncthreads();
        mma_chunk_t<2, 4>(sb + OFF_AH, sb + OFF_AL, sb + OFF_BH, sb + OFF_BL,
                          STR * 2, wm, wn, lane, acc);
        __syncthreads();
    }

#pragma unroll
    for (int mt = 0; mt < 2; mt++)
#pragma unroll
        for (int nt = 0; nt < 4; nt++) {
            float* a4 = &acc[(mt * 4 + nt) * 4];
            int r = row0 + wm + mt * 16 + (lane >> 2);
            int cg = col0 + wn + nt * 8 + (lane & 3) * 2;
            float* p0 = &g_gates[(size_t)r * 1024 + cg];
            float* p1 = &g_gates[(size_t)(r + 8) * 1024 + cg];
            if (ACCUM) {
                float2 o0 = *(float2*)p0, o1 = *(float2*)p1;
                *(float2*)p0 = make_float2(o0.x + a4[0], o0.y + a4[1]);
                *(float2*)p1 = make_float2(o1.x + a4[2], o1.y + a4[3]);
            } else {
                *(float2*)p0 = make_float2(a4[0], a4[1]);
                *(float2*)p1 = make_float2(a4[2], a4[3]);
            }
        }
}

__global__ __launch_bounds__(256) void k_gates768(
    const float* __restrict__ token, const float* __restrict__ query,
    const float* __restrict__ h0)
{
    gates_core<12, false>(token, query, h0, threadIdx.x);
}
__global__ __launch_bounds__(256) void k_gates256()
{
    gates_core<4, true>(nullptr, nullptr, nullptr, threadIdx.x);
}

// =====================================================================
// K5: LSTM elementwise + output writes
// =====================================================================
__global__ __launch_bounds__(256) void k_lstm_ew(
    const float* __restrict__ c0, float* __restrict__ out, int write3)
{
    int n = blockIdx.x;
    int d = threadIdx.x;
    size_t g = (size_t)n * 1024;
    float gi = g_gates[g + d];
    float gf = g_gates[g + 256 + d];
    float gg = g_gates[g + 512 + d];
    float go = g_gates[g + 768 + d];
    float cprev = c0[(size_t)n * Dm + d];
    float cnew = sigm(gf) * cprev + sigm(gi) * tanh_fast(gg);
    float hnew = sigm(go) * tanh_fast(cnew);
    size_t idx = (size_t)n * Dm + d;
    out[idx] = hnew;
    if (write3) {
        out[(size_t)Nn * Dm + idx]     = hnew;
        out[(size_t)2 * Nn * Dm + idx] = cnew;
    }
}

// ---------------- streams/events (static init, outside capture) ----------
static cudaStream_t g_s1 = nullptr;
static cudaEvent_t g_e0 = nullptr, g_e_proj = nullptr, g_e_g768 = nullptr;
static bool g_streams_ok = false;
static struct StreamInit {
    StreamInit() {
        bool ok = true;
        ok &= (cudaStreamCreateWithFlags(&g_s1, cudaStreamNonBlocking) == cudaSuccess);
        ok &= (cudaEventCreateWithFlags(&g_e0, cudaEventDisableTiming) == cudaSuccess);
        ok &= (cudaEventCreateWithFlags(&g_e_proj, cudaEventDisableTiming) == cudaSuccess);
        ok &= (cudaEventCreateWithFlags(&g_e_g768, cudaEventDisableTiming) == cudaSuccess);
        g_streams_ok = ok;
    }
} g_stream_init;

// =====================================================================
// launch
// =====================================================================
extern "C" void kernel_launch(void* const* d_in, const int* in_sizes, int n_in,
                              void* d_out, int out_size)
{
    const float* token  = (const float*)d_in[0];
    const float* h0     = (const float*)d_in[1];
    const float* c0     = (const float*)d_in[2];
    const float* query  = (const float*)d_in[3];
    const float* rp     = (const float*)d_in[4];
    const float* ehs    = (const float*)d_in[5];
    const float* Wvalue = (const float*)d_in[8];
    const float* bvalue = (const float*)d_in[9];
    const float* Woff   = (const float*)d_in[10];
    const float* boff   = (const float*)d_in[11];
    const float* Waw    = (const float*)d_in[12];
    const float* baw    = (const float*)d_in[13];
    const float* Wctx   = (const float*)d_in[14];
    const float* bctx   = (const float*)d_in[15];
    const float* Whs    = (const float*)d_in[16];
    const float* bhs    = (const float*)d_in[17];
    const float* Walpha = (const float*)d_in[18];
    const float* Wih    = (const float*)d_in[20];
    const float* Whh    = (const float*)d_in[21];
    float* out = (float*)d_out;

    cudaFuncSetAttribute(k_value_mma,
                         cudaFuncAttributeMaxDynamicSharedMemorySize, VP_SMEM);
    cudaFuncSetAttribute(k_proj_mma,
                         cudaFuncAttributeMaxDynamicSharedMemorySize, GEMM_SMEM);
    cudaFuncSetAttribute(k_sample_attn,
                         cudaFuncAttributeMaxDynamicSharedMemorySize, S3_SMEM);
    cudaFuncSetAttribute(k_gates768,
                         cudaFuncAttributeMaxDynamicSharedMemorySize, GEMM_SMEM);
    cudaFuncSetAttribute(k_gates256,
                         cudaFuncAttributeMaxDynamicSharedMemorySize, GEMM_SMEM);

    int write3 = (out_size >= 3 * Nn * Dm) ? 1 : 0;
    const int PREP_REST_BLOCKS = (1048576 + 8192 + 262144 + 255) / 256;  // 5152

    if (g_streams_ok) {
        k_prep_B<<<256, 256>>>(Wvalue);
        cudaEventRecord(g_e0, 0);
        cudaStreamWaitEvent(g_s1, g_e0, 0);
        k_prep_rest<<<PREP_REST_BLOCKS, 256, 0, g_s1>>>(Wih, Whh, Wctx, Woff, Waw, Whs);
        k_proj_mma<<<dim3(4, 50), 256, GEMM_SMEM, g_s1>>>(h0, query, boff, baw, bhs, bctx);
        cudaEventRecord(g_e_proj, g_s1);
        k_gates768<<<dim3(8, 50), 256, GEMM_SMEM, g_s1>>>(token, query, h0);
        cudaEventRecord(g_e_g768, g_s1);
        k_value_mma<<<1920, 256, VP_SMEM>>>(ehs, bvalue);
        cudaStreamWaitEvent(0, g_e_proj, 0);
        k_sample_attn<<<Nn, 256, S3_SMEM>>>(rp, Walpha);
        cudaStreamWaitEvent(0, g_e_g768, 0);
        k_gates256<<<dim3(8, 50), 256, GEMM_SMEM>>>();
        k_lstm_ew<<<Nn, 256>>>(c0, out, write3);
    } else {
        k_prep_B<<<256, 256>>>(Wvalue);
        k_prep_rest<<<PREP_REST_BLOCKS, 256>>>(Wih, Whh, Wctx, Woff, Waw, Whs);
        k_proj_mma<<<dim3(4, 50), 256, GEMM_SMEM>>>(h0, query, boff, baw, bhs, bctx);
        k_gates768<<<dim3(8, 50), 256, GEMM_SMEM>>>(token, query, h0);
        k_value_mma<<<1920, 256, VP_SMEM>>>(ehs, bvalue);
        k_sample_attn<<<Nn, 256, S3_SMEM>>>(rp, Walpha);
        k_gates256<<<dim3(8, 50), 256, GEMM_SMEM>>>();
        k_lstm_ew<<<Nn, 256>>>(c0, out, write3);
    }
}

// round 9
// speedup vs baseline: 1.0466x; 1.0466x over previous
#include <cuda_runtime.h>
#include <cuda_bf16.h>
#include <cstdint>

// ---------------- problem constants ----------------
#define Dm 256
#define Hh 8
#define HD 32
#define Ll 4
#define Pp 4
#define Bb 32
#define NQ 100
#define Nn (Bb*NQ)          // 3200
#define T_TOTAL 3840
#define LP 16
#define HLP 128

// ---------------- device scratch ----------------
__device__ float g_value[(size_t)Bb * T_TOTAL * Dm];   // ~126MB
__device__ float g_off[Nn * HLP];
__device__ float g_awl[Nn * HLP];
__device__ float g_hsproj[Nn * Dm];
__device__ float g_attnres[Nn * Dm];
__device__ float g_gates[Nn * 4 * Dm];
__device__ __nv_bfloat16 g_Bh[Dm * Dm];        // W_value^T [n][k]
__device__ __nv_bfloat16 g_Bl[Dm * Dm];
__device__ __nv_bfloat16 g_Gh[1024 * 1024];    // [Wih|Whh] [j][k]
__device__ __nv_bfloat16 g_Gl[1024 * 1024];
__device__ __nv_bfloat16 g_Ch[256 * 32];       // Wctx^T [e][d]
__device__ __nv_bfloat16 g_Cl[256 * 32];
__device__ __nv_bfloat16 g_Ph[512 * 512];      // proj B [n][k]
__device__ __nv_bfloat16 g_Pl[512 * 512];

__device__ __forceinline__ float tanh_fast(float x) {
    float e = __expf(2.0f * x);
    return 1.0f - 2.0f / (e + 1.0f);
}
__device__ __forceinline__ float tanha(float x) {
    float y;
    asm("tanh.approx.f32 %0, %1;" : "=f"(y) : "f"(x));
    return y;
}
__device__ __forceinline__ float sigm(float x) {
    return 1.0f / (1.0f + __expf(-x));
}
__device__ __forceinline__ uint32_t smem_u32(const void* p) {
    uint32_t a;
    asm("{ .reg .u64 t; cvta.to.shared.u64 t, %1; cvt.u32.u64 %0, t; }"
        : "=r"(a) : "l"(p));
    return a;
}
__device__ __forceinline__ void bf16_split(float x, __nv_bfloat16& h, __nv_bfloat16& l) {
    h = __float2bfloat16_rn(x);
    l = __float2bfloat16_rn(x - __bfloat162float(h));
}

// ---------------- mma.sync / ldmatrix ----------------
__device__ __forceinline__ void ldm_x4(uint32_t* r, uint32_t addr) {
    asm volatile("ldmatrix.sync.aligned.m8n8.x4.shared.b16 {%0,%1,%2,%3}, [%4];"
        : "=r"(r[0]), "=r"(r[1]), "=r"(r[2]), "=r"(r[3]) : "r"(addr));
}
#define MMA16816(d, a, b) \
    asm volatile("mma.sync.aligned.m16n8k16.row.col.f32.bf16.bf16.f32 " \
        "{%0,%1,%2,%3}, {%4,%5,%6,%7}, {%8,%9}, {%0,%1,%2,%3};" \
        : "+f"((d)[0]), "+f"((d)[1]), "+f"((d)[2]), "+f"((d)[3]) \
        : "r"((a)[0]), "r"((a)[1]), "r"((a)[2]), "r"((a)[3]), \
          "r"((b)[0]), "r"((b)[1]))

// 3-term fused chunk, TERM-OUTER ordering: for each term, all accumulator
// tiles are independent -> no back-to-back RAW chains on any accumulator.
// Per-accumulator term order (hh, lh, hl) preserved -> bitwise identical.
template<int NT2, int KS>
__device__ __forceinline__ void mma_chunk_t(
    uint32_t aH, uint32_t aL, uint32_t bH, uint32_t bL,
    uint32_t stride2, int wm, int wn, int lane, float* acc)
{
    int arow = lane & 15, acol8 = (lane >> 4) * 8;
    int brow = ((lane >> 4) & 1) * 8 + (lane & 7);
    int bcol8 = ((lane >> 3) & 1) * 8;
#pragma unroll
    for (int ks = 0; ks < KS; ks++) {
        uint32_t Ah[2][4], Al[2][4], Bh[NT2][4], Bl[NT2][4];
#pragma unroll
        for (int mt = 0; mt < 2; mt++) {
            uint32_t off = (uint32_t)(wm + mt * 16 + arow) * stride2
                         + (uint32_t)(ks * 16 + acol8) * 2;
            ldm_x4(Ah[mt], aH + off);
            ldm_x4(Al[mt], aL + off);
        }
#pragma unroll
        for (int nt2 = 0; nt2 < NT2; nt2++) {
            uint32_t off = (uint32_t)(wn + nt2 * 16 + brow) * stride2
                         + (uint32_t)(ks * 16 + bcol8) * 2;
            ldm_x4(Bh[nt2], bH + off);
            ldm_x4(Bl[nt2], bL + off);
        }
        // term 0: Ah x Bh
#pragma unroll
        for (int mt = 0; mt < 2; mt++)
#pragma unroll
            for (int nt = 0; nt < 2 * NT2; nt++)
                MMA16816(acc + (mt * 2 * NT2 + nt) * 4, Ah[mt],
                         (&Bh[nt >> 1][(nt & 1) * 2]));
        // term 1: Al x Bh
#pragma unroll
        for (int mt = 0; mt < 2; mt++)
#pragma unroll
            for (int nt = 0; nt < 2 * NT2; nt++)
                MMA16816(acc + (mt * 2 * NT2 + nt) * 4, Al[mt],
                         (&Bh[nt >> 1][(nt & 1) * 2]));
        // term 2: Ah x Bl
#pragma unroll
        for (int mt = 0; mt < 2; mt++)
#pragma unroll
            for (int nt = 0; nt < 2 * NT2; nt++)
                MMA16816(acc + (mt * 2 * NT2 + nt) * 4, Ah[mt],
                         (&Bl[nt >> 1][(nt & 1) * 2]));
    }
}

#define STR 72
#define OFF_AH 0
#define OFF_AL 9216
#define OFF_BH 18432
#define OFF_BL 36864
#define GEMM_SMEM 55296
#define V_AH 0
#define V_AL 9216
#define V_BH 18432
#define V_BL 55296
#define V_SMEM 92160

// =====================================================================
// K0a: prep W_value split only
// =====================================================================
__global__ __launch_bounds__(256) void k_prep_B(const float* __restrict__ Wvalue)
{
    int idx = blockIdx.x * 256 + threadIdx.x;   // < 65536
    int n = idx >> 8, k = idx & 255;
    __nv_bfloat16 h, l;
    bf16_split(Wvalue[k * Dm + n], h, l);
    g_Bh[idx] = h; g_Bl[idx] = l;
}

// =====================================================================
// K0b: prep remaining weights
// =====================================================================
__global__ __launch_bounds__(256) void k_prep_rest(
    const float* __restrict__ Wih, const float* __restrict__ Whh,
    const float* __restrict__ Wctx,
    const float* __restrict__ Woff, const float* __restrict__ Waw,
    const float* __restrict__ Whs)
{
    int idx = blockIdx.x * 256 + threadIdx.x;
    __nv_bfloat16 h, l;
    if (idx < 1048576) {
        int j = idx >> 10, k = idx & 1023;
        float v = (k < 768) ? Wih[(size_t)j * 768 + k]
                            : Whh[(size_t)j * 256 + (k - 768)];
        bf16_split(v, h, l);
        g_Gh[idx] = h; g_Gl[idx] = l;
    } else if (idx < 1048576 + 8192) {
        int i = idx - 1048576;
        int e = i >> 5, k = i & 31;
        bf16_split(Wctx[k * 256 + e], h, l);
        g_Ch[i] = h; g_Cl[i] = l;
    } else if (idx < 1056768 + 262144) {
        int i = idx - 1056768;
        int n = i >> 9, k = i & 511;
        float v;
        if (n < 128)      v = Woff[k * 128 + n];
        else if (n < 256) v = Waw[k * 128 + (n - 128)];
        else              v = (k < 256) ? Whs[k * 256 + (n - 256)] : 0.f;
        bf16_split(v, h, l);
        g_Ph[i] = h; g_Pl[i] = l;
    }
}

// =====================================================================
// K1: value GEMM (round-5 shape + A register prefetch + term-outer mma)
// M=122880, N=256(full), K=256. grid 1920, BM=64
// =====================================================================
__global__ __launch_bounds__(256, 2) void k_value_mma(
    const float* __restrict__ A, const float* __restrict__ bias)
{
    extern __shared__ char smem[];
    uint32_t sb = smem_u32(smem);
    int tid = threadIdx.x;
    int w = tid >> 5, lane = tid & 31;
    int wm = (w >> 2) * 32, wn = (w & 3) * 64;
    int row0 = blockIdx.x * 64;

    float acc[64];
#pragma unroll
    for (int i = 0; i < 64; i++) acc[i] = 0.f;

    __nv_bfloat16* sAh = (__nv_bfloat16*)(smem + V_AH);
    __nv_bfloat16* sAl = (__nv_bfloat16*)(smem + V_AL);
    __nv_bfloat16* sBh = (__nv_bfloat16*)(smem + V_BH);
    __nv_bfloat16* sBl = (__nv_bfloat16*)(smem + V_BL);

    uint4 pfH[2], pfL[2];
    auto ldA = [&](int c) {
#pragma unroll
        for (int i = 0; i < 2; i++) {
            int g = tid + i * 256;
            int m = g >> 3, kg = g & 7;
            const float* s = A + (size_t)(row0 + m) * Dm + c * 64 + kg * 8;
            float4 v0 = *(const float4*)s;
            float4 v1 = *(const float4*)(s + 4);
            float xs[8] = {v0.x, v0.y, v0.z, v0.w, v1.x, v1.y, v1.z, v1.w};
            __nv_bfloat16 hh[8], ll[8];
#pragma unroll
            for (int j = 0; j < 8; j++) bf16_split(xs[j], hh[j], ll[j]);
            pfH[i] = *(uint4*)hh;
            pfL[i] = *(uint4*)ll;
        }
    };
    auto stsA = [&]() {
#pragma unroll
        for (int i = 0; i < 2; i++) {
            int g = tid + i * 256;
            int m = g >> 3, kg = g & 7;
            *(uint4*)&sAh[m * STR + kg * 8] = pfH[i];
            *(uint4*)&sAl[m * STR + kg * 8] = pfL[i];
        }
    };

    ldA(0);                       // prologue
    for (int c = 0; c < 4; c++) {
        stsA();                   // A chunk c into (just-freed) buffer
        for (int g = tid; g < 2048; g += 256) {   // B chunk c (L2-resident)
            int n = g >> 3, kg = g & 7;
            int gi = n * Dm + c * 64 + kg * 8;
            *(uint4*)&sBh[n * STR + kg * 8] = *(const uint4*)&g_Bh[gi];
            *(uint4*)&sBl[n * STR + kg * 8] = *(const uint4*)&g_Bl[gi];
        }
        __syncthreads();
        if (c < 3) ldA(c + 1);    // LDG latency hides under mma below
        mma_chunk_t<4, 4>(sb + V_AH, sb + V_AL, sb + V_BH, sb + V_BL,
                          STR * 2, wm, wn, lane, acc);
        __syncthreads();
    }

#pragma unroll
    for (int mt = 0; mt < 2; mt++)
#pragma unroll
        for (int nt = 0; nt < 8; nt++) {
            float* a4 = &acc[(mt * 8 + nt) * 4];
            int r = row0 + wm + mt * 16 + (lane >> 2);
            int cg = wn + nt * 8 + (lane & 3) * 2;
            float b0 = __ldg(&bias[cg]), b1 = __ldg(&bias[cg + 1]);
            *(float2*)&g_value[(size_t)r * Dm + cg] =
                make_float2(a4[0] + b0, a4[1] + b1);
            *(float2*)&g_value[(size_t)(r + 8) * Dm + cg] =
                make_float2(a4[2] + b0, a4[3] + b1);
        }
}

// =====================================================================
// K2: proj GEMM. [h0|query](3200x512) @ g_P(512x512). grid (4,50)
// =====================================================================
__global__ __launch_bounds__(256) void k_proj_mma(
    const float* __restrict__ h0, const float* __restrict__ query,
    const float* __restrict__ boff, const float* __restrict__ baw,
    const float* __restrict__ bhs,  const float* __restrict__ bctx)
{
    extern __shared__ char smem[];
    uint32_t sb = smem_u32(smem);
    int tid = threadIdx.x;
    int w = tid >> 5, lane = tid & 31;
    int wm = (w >> 2) * 32, wn = (w & 3) * 32;
    int row0 = blockIdx.y * 64;
    int col0 = blockIdx.x * 128;

    float acc[32];
#pragma unroll
    for (int i = 0; i < 32; i++) acc[i] = 0.f;

    __nv_bfloat16* sAh = (__nv_bfloat16*)(smem + OFF_AH);
    __nv_bfloat16* sAl = (__nv_bfloat16*)(smem + OFF_AL);
    __nv_bfloat16* sBh = (__nv_bfloat16*)(smem + OFF_BH);
    __nv_bfloat16* sBl = (__nv_bfloat16*)(smem + OFF_BL);

    for (int c = 0; c < 8; c++) {
        const float* src = (c < 4) ? h0 : query;
        int kkb = (c & 3) * 64;
        for (int g = tid; g < 512; g += 256) {
            int m = g >> 3, kg = g & 7;
            const float* s = src + (size_t)(row0 + m) * Dm + kkb + kg * 8;
            float4 v0 = *(const float4*)s;
            float4 v1 = *(const float4*)(s + 4);
            float xs[8] = {v0.x, v0.y, v0.z, v0.w, v1.x, v1.y, v1.z, v1.w};
            __nv_bfloat16 hh[8], ll[8];
#pragma unroll
            for (int i = 0; i < 8; i++) bf16_split(xs[i], hh[i], ll[i]);
            *(uint4*)&sAh[m * STR + kg * 8] = *(uint4*)hh;
            *(uint4*)&sAl[m * STR + kg * 8] = *(uint4*)ll;
        }
        for (int g = tid; g < 1024; g += 256) {
            int n = g >> 3, kg = g & 7;
            int gi = (col0 + n) * 512 + c * 64 + kg * 8;
            *(uint4*)&sBh[n * STR + kg * 8] = *(const uint4*)&g_Ph[gi];
            *(uint4*)&sBl[n * STR + kg * 8] = *(const uint4*)&g_Pl[gi];
        }
        __syncthreads();
        mma_chunk_t<2, 4>(sb + OFF_AH, sb + OFF_AL, sb + OFF_BH, sb + OFF_BL,
                          STR * 2, wm, wn, lane, acc);
        __syncthreads();
    }

    int bx = blockIdx.x;
#pragma unroll
    for (int mt = 0; mt < 2; mt++)
#pragma unroll
        for (int nt = 0; nt < 4; nt++) {
            float* a4 = &acc[(mt * 4 + nt) * 4];
            int r = row0 + wm + mt * 16 + (lane >> 2);
            int cl = wn + nt * 8 + (lane & 3) * 2;
            if (bx == 0) {
                float b0 = __ldg(&boff[cl]), b1 = __ldg(&boff[cl + 1]);
                *(float2*)&g_off[r * 128 + cl] = make_float2(a4[0] + b0, a4[1] + b1);
                *(float2*)&g_off[(r + 8) * 128 + cl] = make_float2(a4[2] + b0, a4[3] + b1);
            } else if (bx == 1) {
                float b0 = __ldg(&baw[cl]), b1 = __ldg(&baw[cl + 1]);
                *(float2*)&g_awl[r * 128 + cl] = make_float2(a4[0] + b0, a4[1] + b1);
                *(float2*)&g_awl[(r + 8) * 128 + cl] = make_float2(a4[2] + b0, a4[3] + b1);
            } else {
                int col = (bx - 2) * 128 + cl;
                float b0 = __ldg(&bhs[col]) + __ldg(&bctx[col]);
                float b1 = __ldg(&bhs[col + 1]) + __ldg(&bctx[col + 1]);
                *(float2*)&g_hsproj[r * 256 + col] = make_float2(a4[0] + b0, a4[1] + b1);
                *(float2*)&g_hsproj[(r + 8) * 256 + col] = make_float2(a4[2] + b0, a4[3] + b1);
            }
        }
}

// =====================================================================
// K3: sample + additive attention
// =====================================================================
#define A3STR 40
#define S3_AH  0
#define S3_AL  10240
#define S3_BH  20480
#define S3_BL  40960
#define S3_ADD 61440
#define S3_WA  62464
#define S3_AW  63488
#define S3_SC  64000
#define S3_SMEM 64512

__global__ __launch_bounds__(256) void k_sample_attn(
    const float* __restrict__ rp,
    const float* __restrict__ Walpha)
{
    extern __shared__ char sm3[];
    __nv_bfloat16* sAh3 = (__nv_bfloat16*)(sm3 + S3_AH);
    __nv_bfloat16* sAl3 = (__nv_bfloat16*)(sm3 + S3_AL);
    __nv_bfloat16* sBh3 = (__nv_bfloat16*)(sm3 + S3_BH);
    __nv_bfloat16* sBl3 = (__nv_bfloat16*)(sm3 + S3_BL);
    float* add_s = (float*)(sm3 + S3_ADD);
    float* Wa_s  = (float*)(sm3 + S3_WA);
    float* aw_s  = (float*)(sm3 + S3_AW);
    float* sc_s  = (float*)(sm3 + S3_SC);

    int n = blockIdx.x;
    int tid = threadIdx.x;
    int w = tid >> 5, lane = tid & 31;
    int b = n / NQ;

    for (int g = tid; g < 1024; g += 256) {
        int r = g >> 2, kg = (g & 3) * 8;
        *(uint4*)&sBh3[r * A3STR + kg] = *(const uint4*)&g_Ch[r * 32 + kg];
        *(uint4*)&sBl3[r * A3STR + kg] = *(const uint4*)&g_Cl[r * 32 + kg];
    }
    if (tid < 128) { aw_s[tid] = g_awl[n * 128 + tid]; sc_s[tid] = 0.f; }
    add_s[tid] = g_hsproj[n * 256 + tid];
    Wa_s[tid] = Walpha[tid];
    __syncthreads();

    if (lane < 16) {
        float v = aw_s[w * 16 + lane];
        float mx = v;
#pragma unroll
        for (int o = 8; o > 0; o >>= 1)
            mx = fmaxf(mx, __shfl_xor_sync(0x0000ffffu, mx, o, 16));
        float ev = __expf(v - mx);
        float s = ev;
#pragma unroll
        for (int o = 8; o > 0; o >>= 1)
            s += __shfl_xor_sync(0x0000ffffu, s, o, 16);
        aw_s[w * 16 + lane] = ev / s;
    }
    __syncthreads();

    {
        const int TLS[4]    = {2048, 1024, 512, 256};
        const int STARTS[4] = {0, 2048, 3072, 3584};
        int pair = tid >> 1, half = tid & 1;
        int h2 = pair >> 4, lp = pair & 15, l = lp >> 2;
        int Tl = TLS[l], st = STARTS[l];
        float ref = rp[n * Ll + l];
        float off = g_off[n * HLP + pair];
        float aw = aw_s[pair];
        float x = ref * (float)Tl + off - 0.5f;
        float xf = floorf(x);
        float w1 = x - xf, w0 = 1.0f - w1;
        int i0 = (int)xf, i1 = i0 + 1;
        float wa0 = aw * w0 * ((i0 >= 0 && i0 < Tl) ? 1.f : 0.f);
        float wa1 = aw * w1 * ((i1 >= 0 && i1 < Tl) ? 1.f : 0.f);
        int c0i = min(max(i0, 0), Tl - 1);
        int c1i = min(max(i1, 0), Tl - 1);
        size_t base0 = ((size_t)(b * T_TOTAL + st + c0i)) * Dm + h2 * HD + half * 16;
        size_t base1 = ((size_t)(b * T_TOTAL + st + c1i)) * Dm + h2 * HD + half * 16;
#pragma unroll
        for (int q4 = 0; q4 < 4; q4++) {
            float4 v0 = *(const float4*)&g_value[base0 + q4 * 4];
            float4 v1 = *(const float4*)&g_value[base1 + q4 * 4];
            float fx[4];
            fx[0] = wa0 * v0.x + wa1 * v1.x;
            fx[1] = wa0 * v0.y + wa1 * v1.y;
            fx[2] = wa0 * v0.z + wa1 * v1.z;
            fx[3] = wa0 * v0.w + wa1 * v1.w;
            __nv_bfloat16 hh[4], ll[4];
#pragma unroll
            for (int i = 0; i < 4; i++) bf16_split(fx[i], hh[i], ll[i]);
            int d = half * 16 + q4 * 4;
            *(uint2*)&sAh3[pair * A3STR + d] = *(uint2*)hh;
            *(uint2*)&sAl3[pair * A3STR + d] = *(uint2*)ll;
        }
    }
    __syncthreads();

    uint32_t aH = smem_u32(sAh3), aL = smem_u32(sAl3);
    uint32_t bH = smem_u32(sBh3), bL = smem_u32(sBl3);
    int wm = (w >> 1) * 32, wnl = (w & 1) * 32;
    float scoreacc[2][2] = {{0.f, 0.f}, {0.f, 0.f}};

#pragma unroll
    for (int pass = 0; pass < 4; pass++) {
        uint32_t boff2 = (uint32_t)(pass * 64 * A3STR * 2);
        float acc[32];
#pragma unroll
        for (int i = 0; i < 32; i++) acc[i] = 0.f;
        mma_chunk_t<2, 2>(aH, aL, bH + boff2, bL + boff2,
                          A3STR * 2, wm, wnl, lane, acc);
#pragma unroll
        for (int mt = 0; mt < 2; mt++)
#pragma unroll
            for (int nt = 0; nt < 4; nt++) {
                float* a4 = &acc[(mt * 4 + nt) * 4];
                int e0 = pass * 64 + wnl + nt * 8 + (lane & 3) * 2;
                scoreacc[mt][0] += tanha(a4[0] + add_s[e0]) * Wa_s[e0];
                scoreacc[mt][0] += tanha(a4[1] + add_s[e0 + 1]) * Wa_s[e0 + 1];
                scoreacc[mt][1] += tanha(a4[2] + add_s[e0]) * Wa_s[e0];
                scoreacc[mt][1] += tanha(a4[3] + add_s[e0 + 1]) * Wa_s[e0 + 1];
            }
    }

#pragma unroll
    for (int mt = 0; mt < 2; mt++) {
        float s0 = scoreacc[mt][0], s1 = scoreacc[mt][1];
        s0 += __shfl_xor_sync(0xffffffffu, s0, 1);
        s0 += __shfl_xor_sync(0xffffffffu, s0, 2);
        s1 += __shfl_xor_sync(0xffffffffu, s1, 1);
        s1 += __shfl_xor_sync(0xffffffffu, s1, 2);
        if ((lane & 3) == 0) {
            atomicAdd(&sc_s[wm + mt * 16 + (lane >> 2)], s0);
            atomicAdd(&sc_s[wm + mt * 16 + 8 + (lane >> 2)], s1);
        }
    }
    __syncthreads();

    if (lane < 16) {
        float v = sc_s[w * 16 + lane];
        float mx = v;
#pragma unroll
        for (int o = 8; o > 0; o >>= 1)
            mx = fmaxf(mx, __shfl_xor_sync(0x0000ffffu, mx, o, 16));
        float ev = __expf(v - mx);
        float s = ev;
#pragma unroll
        for (int o = 8; o > 0; o >>= 1)
            s += __shfl_xor_sync(0x0000ffffu, s, o, 16);
        sc_s[w * 16 + lane] = ev / s;
    }
    __syncwarp();

    {
        float accw = 0.f;
#pragma unroll
        for (int p = 0; p < 16; p++) {
            int r = (w * 16 + p) * A3STR + lane;
            accw += sc_s[w * 16 + p] *
                    (__bfloat162float(sAh3[r]) + __bfloat162float(sAl3[r]));
        }
        g_attnres[(size_t)n * Dm + w * HD + lane] = accw;
    }
}

// =====================================================================
// K4a/K4b: gates GEMMs
// =====================================================================
template<int NCHUNK, bool ACCUM>
__device__ __forceinline__ void gates_core(
    const float* token, const float* query, const float* h0, int tid)
{
    extern __shared__ char smem[];
    uint32_t sb = smem_u32(smem);
    int w = tid >> 5, lane = tid & 31;
    int wm = (w >> 2) * 32, wn = (w & 3) * 32;
    int row0 = blockIdx.y * 64;
    int col0 = blockIdx.x * 128;

    float acc[32];
#pragma unroll
    for (int i = 0; i < 32; i++) acc[i] = 0.f;

    __nv_bfloat16* sAh = (__nv_bfloat16*)(smem + OFF_AH);
    __nv_bfloat16* sAl = (__nv_bfloat16*)(smem + OFF_AL);
    __nv_bfloat16* sBh = (__nv_bfloat16*)(smem + OFF_BH);
    __nv_bfloat16* sBl = (__nv_bfloat16*)(smem + OFF_BL);

    const int segbase[3] = {0, 512, 768};
    for (int c = 0; c < NCHUNK; c++) {
        const float* src;
        int kcol;
        if (ACCUM) { src = g_attnres; kcol = 256 + c * 64; }
        else {
            int seg = c >> 2;
            src = (seg == 0) ? token : (seg == 1) ? query : h0;
            kcol = segbase[seg] + (c & 3) * 64;
        }
        int kkb = (c & 3) * 64;
        for (int g = tid; g < 512; g += 256) {
            int m = g >> 3, kg = g & 7;
            const float* s = src + (size_t)(row0 + m) * Dm + kkb + kg * 8;
            float4 v0 = *(const float4*)s;
            float4 v1 = *(const float4*)(s + 4);
            float xs[8] = {v0.x, v0.y, v0.z, v0.w, v1.x, v1.y, v1.z, v1.w};
            __nv_bfloat16 hh[8], ll[8];
#pragma unroll
            for (int i = 0; i < 8; i++) bf16_split(xs[i], hh[i], ll[i]);
            *(uint4*)&sAh[m * STR + kg * 8] = *(uint4*)hh;
            *(uint4*)&sAl[m * STR + kg * 8] = *(uint4*)ll;
        }
        for (int g = tid; g < 1024; g += 256) {
            int n = g >> 3, kg = g & 7;
            size_t gi = (size_t)(col0 + n) * 1024 + kcol + kg * 8;
            *(uint4*)&sBh[n * STR + kg * 8] = *(const uint4*)&g_Gh[gi];
            *(uint4*)&sBl[n * STR + kg * 8] = *(const uint4*)&g_Gl[gi];
        }
        __syncthreads();
        mma_chunk_t<2, 4>(sb + OFF_AH, sb + OFF_AL, sb + OFF_BH, sb + OFF_BL,
                          STR * 2, wm, wn, lane, acc);
        __syncthreads();
    }

#pragma unroll
    for (int mt = 0; mt < 2; mt++)
#pragma unroll
        for (int nt = 0; nt < 4; nt++) {
            float* a4 = &acc[(mt * 4 + nt) * 4];
            int r = row0 + wm + mt * 16 + (lane >> 2);
            int cg = col0 + wn + nt * 8 + (lane & 3) * 2;
            float* p0 = &g_gates[(size_t)r * 1024 + cg];
            float* p1 = &g_gates[(size_t)(r + 8) * 1024 + cg];
            if (ACCUM) {
                float2 o0 = *(float2*)p0, o1 = *(float2*)p1;
                *(float2*)p0 = make_float2(o0.x + a4[0], o0.y + a4[1]);
                *(float2*)p1 = make_float2(o1.x + a4[2], o1.y + a4[3]);
            } else {
                *(float2*)p0 = make_float2(a4[0], a4[1]);
                *(float2*)p1 = make_float2(a4[2], a4[3]);
            }
        }
}

__global__ __launch_bounds__(256) void k_gates768(
    const float* __restrict__ token, const float* __restrict__ query,
    const float* __restrict__ h0)
{
    gates_core<12, false>(token, query, h0, threadIdx.x);
}
__global__ __launch_bounds__(256) void k_gates256()
{
    gates_core<4, true>(nullptr, nullptr, nullptr, threadIdx.x);
}

// =====================================================================
// K5: LSTM elementwise + output writes
// =====================================================================
__global__ __launch_bounds__(256) void k_lstm_ew(
    const float* __restrict__ c0, float* __restrict__ out, int write3)
{
    int n = blockIdx.x;
    int d = threadIdx.x;
    size_t g = (size_t)n * 1024;
    float gi = g_gates[g + d];
    float gf = g_gates[g + 256 + d];
    float gg = g_gates[g + 512 + d];
    float go = g_gates[g + 768 + d];
    float cprev = c0[(size_t)n * Dm + d];
    float cnew = sigm(gf) * cprev + sigm(gi) * tanh_fast(gg);
    float hnew = sigm(go) * tanh_fast(cnew);
    size_t idx = (size_t)n * Dm + d;
    out[idx] = hnew;
    if (write3) {
        out[(size_t)Nn * Dm + idx]     = hnew;
        out[(size_t)2 * Nn * Dm + idx] = cnew;
    }
}

// ---------------- streams/events (static init, outside capture) ----------
static cudaStream_t g_s1 = nullptr;
static cudaEvent_t g_e0 = nullptr, g_e_proj = nullptr, g_e_g768 = nullptr;
static bool g_streams_ok = false;
static struct StreamInit {
    StreamInit() {
        bool ok = true;
        ok &= (cudaStreamCreateWithFlags(&g_s1, cudaStreamNonBlocking) == cudaSuccess);
        ok &= (cudaEventCreateWithFlags(&g_e0, cudaEventDisableTiming) == cudaSuccess);
        ok &= (cudaEventCreateWithFlags(&g_e_proj, cudaEventDisableTiming) == cudaSuccess);
        ok &= (cudaEventCreateWithFlags(&g_e_g768, cudaEventDisableTiming) == cudaSuccess);
        g_streams_ok = ok;
    }
} g_stream_init;

// =====================================================================
// launch
// =====================================================================
extern "C" void kernel_launch(void* const* d_in, const int* in_sizes, int n_in,
                              void* d_out, int out_size)
{
    const float* token  = (const float*)d_in[0];
    const float* h0     = (const float*)d_in[1];
    const float* c0     = (const float*)d_in[2];
    const float* query  = (const float*)d_in[3];
    const float* rp     = (const float*)d_in[4];
    const float* ehs    = (const float*)d_in[5];
    const float* Wvalue = (const float*)d_in[8];
    const float* bvalue = (const float*)d_in[9];
    const float* Woff   = (const float*)d_in[10];
    const float* boff   = (const float*)d_in[11];
    const float* Waw    = (const float*)d_in[12];
    const float* baw    = (const float*)d_in[13];
    const float* Wctx   = (const float*)d_in[14];
    const float* bctx   = (const float*)d_in[15];
    const float* Whs    = (const float*)d_in[16];
    const float* bhs    = (const float*)d_in[17];
    const float* Walpha = (const float*)d_in[18];
    const float* Wih    = (const float*)d_in[20];
    const float* Whh    = (const float*)d_in[21];
    float* out = (float*)d_out;

    cudaFuncSetAttribute(k_value_mma,
                         cudaFuncAttributeMaxDynamicSharedMemorySize, V_SMEM);
    cudaFuncSetAttribute(k_proj_mma,
                         cudaFuncAttributeMaxDynamicSharedMemorySize, GEMM_SMEM);
    cudaFuncSetAttribute(k_sample_attn,
                         cudaFuncAttributeMaxDynamicSharedMemorySize, S3_SMEM);
    cudaFuncSetAttribute(k_gates768,
                         cudaFuncAttributeMaxDynamicSharedMemorySize, GEMM_SMEM);
    cudaFuncSetAttribute(k_gates256,
                         cudaFuncAttributeMaxDynamicSharedMemorySize, GEMM_SMEM);

    int write3 = (out_size >= 3 * Nn * Dm) ? 1 : 0;
    const int PREP_REST_BLOCKS = (1048576 + 8192 + 262144 + 255) / 256;  // 5152

    if (g_streams_ok) {
        k_prep_B<<<256, 256>>>(Wvalue);
        cudaEventRecord(g_e0, 0);
        cudaStreamWaitEvent(g_s1, g_e0, 0);
        k_prep_rest<<<PREP_REST_BLOCKS, 256, 0, g_s1>>>(Wih, Whh, Wctx, Woff, Waw, Whs);
        k_proj_mma<<<dim3(4, 50), 256, GEMM_SMEM, g_s1>>>(h0, query, boff, baw, bhs, bctx);
        cudaEventRecord(g_e_proj, g_s1);
        k_gates768<<<dim3(8, 50), 256, GEMM_SMEM, g_s1>>>(token, query, h0);
        cudaEventRecord(g_e_g768, g_s1);
        k_value_mma<<<1920, 256, V_SMEM>>>(ehs, bvalue);
        cudaStreamWaitEvent(0, g_e_proj, 0);
        k_sample_attn<<<Nn, 256, S3_SMEM>>>(rp, Walpha);
        cudaStreamWaitEvent(0, g_e_g768, 0);
        k_gates256<<<dim3(8, 50), 256, GEMM_SMEM>>>();
        k_lstm_ew<<<Nn, 256>>>(c0, out, write3);
    } else {
        k_prep_B<<<256, 256>>>(Wvalue);
        k_prep_rest<<<PREP_REST_BLOCKS, 256>>>(Wih, Whh, Wctx, Woff, Waw, Whs);
        k_proj_mma<<<dim3(4, 50), 256, GEMM_SMEM>>>(h0, query, boff, baw, bhs, bctx);
        k_gates768<<<dim3(8, 50), 256, GEMM_SMEM>>>(token, query, h0);
        k_value_mma<<<1920, 256, V_SMEM>>>(ehs, bvalue);
        k_sample_attn<<<Nn, 256, S3_SMEM>>>(rp, Walpha);
        k_gates256<<<dim3(8, 50), 256, GEMM_SMEM>>>();
        k_lstm_ew<<<Nn, 256>>>(c0, out, write3);
    }
}

// round 10
// speedup vs baseline: 1.2488x; 1.1932x over previous
#include <cuda_runtime.h>
#include <cuda_fp16.h>
#include <cstdint>

// ---------------- problem constants ----------------
#define Dm 256
#define Hh 8
#define HD 32
#define Ll 4
#define Pp 4
#define Bb 32
#define NQ 100
#define Nn (Bb*NQ)          // 3200
#define T_TOTAL 3840
#define LP 16
#define HLP 128

// ---------------- device scratch ----------------
__device__ float g_value[(size_t)Bb * T_TOTAL * Dm];   // ~126MB
__device__ float g_off[Nn * HLP];
__device__ float g_awl[Nn * HLP];
__device__ float g_hsproj[Nn * Dm];
__device__ float g_attnres[Nn * Dm];
__device__ float g_gates[Nn * 4 * Dm];
// weights: SINGLE fp16 (B-operand rounding carries the 2^-11 error budget)
__device__ __half g_Bf[Dm * Dm];        // W_value^T [n][k]
__device__ __half g_Gf[1024 * 1024];    // [Wih|Whh] [j][k]
__device__ __half g_Cf[256 * 32];       // Wctx^T [e][d]
__device__ __half g_Pf[512 * 512];      // proj B [n][k]

__device__ __forceinline__ float tanh_fast(float x) {
    float e = __expf(2.0f * x);
    return 1.0f - 2.0f / (e + 1.0f);
}
__device__ __forceinline__ float tanha(float x) {
    float y;
    asm("tanh.approx.f32 %0, %1;" : "=f"(y) : "f"(x));
    return y;
}
__device__ __forceinline__ float sigm(float x) {
    return 1.0f / (1.0f + __expf(-x));
}
__device__ __forceinline__ uint32_t smem_u32(const void* p) {
    uint32_t a;
    asm("{ .reg .u64 t; cvta.to.shared.u64 t, %1; cvt.u32.u64 %0, t; }"
        : "=r"(a) : "l"(p));
    return a;
}
// fp16 split: A = h + l, exact to ~2^-21
__device__ __forceinline__ void fp16_split(float x, __half& h, __half& l) {
    h = __float2half_rn(x);
    l = __float2half_rn(x - __half2float(h));
}

// ---------------- mma.sync / ldmatrix (fp16) ----------------
__device__ __forceinline__ void ldm_x4(uint32_t* r, uint32_t addr) {
    asm volatile("ldmatrix.sync.aligned.m8n8.x4.shared.b16 {%0,%1,%2,%3}, [%4];"
        : "=r"(r[0]), "=r"(r[1]), "=r"(r[2]), "=r"(r[3]) : "r"(addr));
}
#define MMAH(d, a, b) \
    asm volatile("mma.sync.aligned.m16n8k16.row.col.f32.f16.f16.f32 " \
        "{%0,%1,%2,%3}, {%4,%5,%6,%7}, {%8,%9}, {%0,%1,%2,%3};" \
        : "+f"((d)[0]), "+f"((d)[1]), "+f"((d)[2]), "+f"((d)[3]) \
        : "r"((a)[0]), "r"((a)[1]), "r"((a)[2]), "r"((a)[3]), \
          "r"((b)[0]), "r"((b)[1]))

// 2-term chunk: (Ah + Al) x Bf. Term-outer; per-acc order fixed.
template<int NT2, int KS>
__device__ __forceinline__ void mma_chunk2(
    uint32_t aH, uint32_t aL, uint32_t bF,
    uint32_t stride2, int wm, int wn, int lane, float* acc)
{
    int arow = lane & 15, acol8 = (lane >> 4) * 8;
    int brow = ((lane >> 4) & 1) * 8 + (lane & 7);
    int bcol8 = ((lane >> 3) & 1) * 8;
#pragma unroll
    for (int ks = 0; ks < KS; ks++) {
        uint32_t Ah[2][4], Al[2][4], B[NT2][4];
#pragma unroll
        for (int mt = 0; mt < 2; mt++) {
            uint32_t off = (uint32_t)(wm + mt * 16 + arow) * stride2
                         + (uint32_t)(ks * 16 + acol8) * 2;
            ldm_x4(Ah[mt], aH + off);
            ldm_x4(Al[mt], aL + off);
        }
#pragma unroll
        for (int nt2 = 0; nt2 < NT2; nt2++) {
            uint32_t off = (uint32_t)(wn + nt2 * 16 + brow) * stride2
                         + (uint32_t)(ks * 16 + bcol8) * 2;
            ldm_x4(B[nt2], bF + off);
        }
#pragma unroll
        for (int mt = 0; mt < 2; mt++)
#pragma unroll
            for (int nt = 0; nt < 2 * NT2; nt++)
                MMAH(acc + (mt * 2 * NT2 + nt) * 4, Ah[mt],
                     (&B[nt >> 1][(nt & 1) * 2]));
#pragma unroll
        for (int mt = 0; mt < 2; mt++)
#pragma unroll
            for (int nt = 0; nt < 2 * NT2; nt++)
                MMAH(acc + (mt * 2 * NT2 + nt) * 4, Al[mt],
                     (&B[nt >> 1][(nt & 1) * 2]));
    }
}

#define STR 72
// generic GEMM smem: A h(9216)+l(9216), B single 128x72x2 = 18432
#define OFF_AH 0
#define OFF_AL 9216
#define OFF_BF 18432
#define GEMM_SMEM 36864
// value: A h+l 18432, B single 256x72x2 = 36864
#define V_AH 0
#define V_AL 9216
#define V_BF 18432
#define V_SMEM 55296

// =====================================================================
// K0a: prep W_value -> fp16 single (transposed)
// =====================================================================
__global__ __launch_bounds__(256) void k_prep_B(const float* __restrict__ Wvalue)
{
    int idx = blockIdx.x * 256 + threadIdx.x;   // < 65536
    int n = idx >> 8, k = idx & 255;
    g_Bf[idx] = __float2half_rn(Wvalue[k * Dm + n]);
}

// =====================================================================
// K0b: prep remaining weights -> fp16 single
// =====================================================================
__global__ __launch_bounds__(256) void k_prep_rest(
    const float* __restrict__ Wih, const float* __restrict__ Whh,
    const float* __restrict__ Wctx,
    const float* __restrict__ Woff, const float* __restrict__ Waw,
    const float* __restrict__ Whs)
{
    int idx = blockIdx.x * 256 + threadIdx.x;
    if (idx < 1048576) {
        int j = idx >> 10, k = idx & 1023;
        float v = (k < 768) ? Wih[(size_t)j * 768 + k]
                            : Whh[(size_t)j * 256 + (k - 768)];
        g_Gf[idx] = __float2half_rn(v);
    } else if (idx < 1048576 + 8192) {
        int i = idx - 1048576;
        int e = i >> 5, k = i & 31;
        g_Cf[i] = __float2half_rn(Wctx[k * 256 + e]);
    } else if (idx < 1056768 + 262144) {
        int i = idx - 1056768;
        int n = i >> 9, k = i & 511;
        float v;
        if (n < 128)      v = Woff[k * 128 + n];
        else if (n < 256) v = Waw[k * 128 + (n - 128)];
        else              v = (k < 256) ? Whs[k * 256 + (n - 256)] : 0.f;
        g_Pf[i] = __float2half_rn(v);
    }
}

// =====================================================================
// K1: value GEMM (fp16 2-term). M=122880, N=256, K=256. grid 1920, BM=64
// =====================================================================
__global__ __launch_bounds__(256, 2) void k_value_mma(
    const float* __restrict__ A, const float* __restrict__ bias)
{
    extern __shared__ char smem[];
    uint32_t sb = smem_u32(smem);
    int tid = threadIdx.x;
    int w = tid >> 5, lane = tid & 31;
    int wm = (w >> 2) * 32, wn = (w & 3) * 64;
    int row0 = blockIdx.x * 64;

    float acc[64];
#pragma unroll
    for (int i = 0; i < 64; i++) acc[i] = 0.f;

    __half* sAh = (__half*)(smem + V_AH);
    __half* sAl = (__half*)(smem + V_AL);
    __half* sBf = (__half*)(smem + V_BF);

    uint4 pfH[2], pfL[2];
    auto ldA = [&](int c) {
#pragma unroll
        for (int i = 0; i < 2; i++) {
            int g = tid + i * 256;
            int m = g >> 3, kg = g & 7;
            const float* s = A + (size_t)(row0 + m) * Dm + c * 64 + kg * 8;
            float4 v0 = *(const float4*)s;
            float4 v1 = *(const float4*)(s + 4);
            float xs[8] = {v0.x, v0.y, v0.z, v0.w, v1.x, v1.y, v1.z, v1.w};
            __half hh[8], ll[8];
#pragma unroll
            for (int j = 0; j < 8; j++) fp16_split(xs[j], hh[j], ll[j]);
            pfH[i] = *(uint4*)hh;
            pfL[i] = *(uint4*)ll;
        }
    };
    auto stsA = [&]() {
#pragma unroll
        for (int i = 0; i < 2; i++) {
            int g = tid + i * 256;
            int m = g >> 3, kg = g & 7;
            *(uint4*)&sAh[m * STR + kg * 8] = pfH[i];
            *(uint4*)&sAl[m * STR + kg * 8] = pfL[i];
        }
    };

    ldA(0);
    for (int c = 0; c < 4; c++) {
        stsA();
        for (int g = tid; g < 2048; g += 256) {   // B chunk (single fp16)
            int n = g >> 3, kg = g & 7;
            int gi = n * Dm + c * 64 + kg * 8;
            *(uint4*)&sBf[n * STR + kg * 8] = *(const uint4*)&g_Bf[gi];
        }
        __syncthreads();
        if (c < 3) ldA(c + 1);
        mma_chunk2<4, 4>(sb + V_AH, sb + V_AL, sb + V_BF,
                         STR * 2, wm, wn, lane, acc);
        __syncthreads();
    }

#pragma unroll
    for (int mt = 0; mt < 2; mt++)
#pragma unroll
        for (int nt = 0; nt < 8; nt++) {
            float* a4 = &acc[(mt * 8 + nt) * 4];
            int r = row0 + wm + mt * 16 + (lane >> 2);
            int cg = wn + nt * 8 + (lane & 3) * 2;
            float b0 = __ldg(&bias[cg]), b1 = __ldg(&bias[cg + 1]);
            *(float2*)&g_value[(size_t)r * Dm + cg] =
                make_float2(a4[0] + b0, a4[1] + b1);
            *(float2*)&g_value[(size_t)(r + 8) * Dm + cg] =
                make_float2(a4[2] + b0, a4[3] + b1);
        }
}

// =====================================================================
// K2: proj GEMM. [h0|query](3200x512) @ g_P(512x512). grid (4,50)
// =====================================================================
__global__ __launch_bounds__(256) void k_proj_mma(
    const float* __restrict__ h0, const float* __restrict__ query,
    const float* __restrict__ boff, const float* __restrict__ baw,
    const float* __restrict__ bhs,  const float* __restrict__ bctx)
{
    extern __shared__ char smem[];
    uint32_t sb = smem_u32(smem);
    int tid = threadIdx.x;
    int w = tid >> 5, lane = tid & 31;
    int wm = (w >> 2) * 32, wn = (w & 3) * 32;
    int row0 = blockIdx.y * 64;
    int col0 = blockIdx.x * 128;

    float acc[32];
#pragma unroll
    for (int i = 0; i < 32; i++) acc[i] = 0.f;

    __half* sAh = (__half*)(smem + OFF_AH);
    __half* sAl = (__half*)(smem + OFF_AL);
    __half* sBf = (__half*)(smem + OFF_BF);

    for (int c = 0; c < 8; c++) {
        const float* src = (c < 4) ? h0 : query;
        int kkb = (c & 3) * 64;
        for (int g = tid; g < 512; g += 256) {
            int m = g >> 3, kg = g & 7;
            const float* s = src + (size_t)(row0 + m) * Dm + kkb + kg * 8;
            float4 v0 = *(const float4*)s;
            float4 v1 = *(const float4*)(s + 4);
            float xs[8] = {v0.x, v0.y, v0.z, v0.w, v1.x, v1.y, v1.z, v1.w};
            __half hh[8], ll[8];
#pragma unroll
            for (int i = 0; i < 8; i++) fp16_split(xs[i], hh[i], ll[i]);
            *(uint4*)&sAh[m * STR + kg * 8] = *(uint4*)hh;
            *(uint4*)&sAl[m * STR + kg * 8] = *(uint4*)ll;
        }
        for (int g = tid; g < 1024; g += 256) {
            int n = g >> 3, kg = g & 7;
            int gi = (col0 + n) * 512 + c * 64 + kg * 8;
            *(uint4*)&sBf[n * STR + kg * 8] = *(const uint4*)&g_Pf[gi];
        }
        __syncthreads();
        mma_chunk2<2, 4>(sb + OFF_AH, sb + OFF_AL, sb + OFF_BF,
                         STR * 2, wm, wn, lane, acc);
        __syncthreads();
    }

    int bx = blockIdx.x;
#pragma unroll
    for (int mt = 0; mt < 2; mt++)
#pragma unroll
        for (int nt = 0; nt < 4; nt++) {
            float* a4 = &acc[(mt * 4 + nt) * 4];
            int r = row0 + wm + mt * 16 + (lane >> 2);
            int cl = wn + nt * 8 + (lane & 3) * 2;
            if (bx == 0) {
                float b0 = __ldg(&boff[cl]), b1 = __ldg(&boff[cl + 1]);
                *(float2*)&g_off[r * 128 + cl] = make_float2(a4[0] + b0, a4[1] + b1);
                *(float2*)&g_off[(r + 8) * 128 + cl] = make_float2(a4[2] + b0, a4[3] + b1);
            } else if (bx == 1) {
                float b0 = __ldg(&baw[cl]), b1 = __ldg(&baw[cl + 1]);
                *(float2*)&g_awl[r * 128 + cl] = make_float2(a4[0] + b0, a4[1] + b1);
                *(float2*)&g_awl[(r + 8) * 128 + cl] = make_float2(a4[2] + b0, a4[3] + b1);
            } else {
                int col = (bx - 2) * 128 + cl;
                float b0 = __ldg(&bhs[col]) + __ldg(&bctx[col]);
                float b1 = __ldg(&bhs[col + 1]) + __ldg(&bctx[col + 1]);
                *(float2*)&g_hsproj[r * 256 + col] = make_float2(a4[0] + b0, a4[1] + b1);
                *(float2*)&g_hsproj[(r + 8) * 256 + col] = make_float2(a4[2] + b0, a4[3] + b1);
            }
        }
}

// =====================================================================
// K3: sample + additive attention (fp16 2-term)
// =====================================================================
#define A3STR 40
#define S3_AH  0
#define S3_AL  10240
#define S3_BF  20480
#define S3_ADD 40960
#define S3_WA  41984
#define S3_AW  43008
#define S3_SC  43520
#define S3_SMEM 44032

__global__ __launch_bounds__(256) void k_sample_attn(
    const float* __restrict__ rp,
    const float* __restrict__ Walpha)
{
    extern __shared__ char sm3[];
    __half* sAh3 = (__half*)(sm3 + S3_AH);
    __half* sAl3 = (__half*)(sm3 + S3_AL);
    __half* sBf3 = (__half*)(sm3 + S3_BF);
    float* add_s = (float*)(sm3 + S3_ADD);
    float* Wa_s  = (float*)(sm3 + S3_WA);
    float* aw_s  = (float*)(sm3 + S3_AW);
    float* sc_s  = (float*)(sm3 + S3_SC);

    int n = blockIdx.x;
    int tid = threadIdx.x;
    int w = tid >> 5, lane = tid & 31;
    int b = n / NQ;

    for (int g = tid; g < 1024; g += 256) {
        int r = g >> 2, kg = (g & 3) * 8;
        *(uint4*)&sBf3[r * A3STR + kg] = *(const uint4*)&g_Cf[r * 32 + kg];
    }
    if (tid < 128) { aw_s[tid] = g_awl[n * 128 + tid]; sc_s[tid] = 0.f; }
    add_s[tid] = g_hsproj[n * 256 + tid];
    Wa_s[tid] = Walpha[tid];
    __syncthreads();

    if (lane < 16) {
        float v = aw_s[w * 16 + lane];
        float mx = v;
#pragma unroll
        for (int o = 8; o > 0; o >>= 1)
            mx = fmaxf(mx, __shfl_xor_sync(0x0000ffffu, mx, o, 16));
        float ev = __expf(v - mx);
        float s = ev;
#pragma unroll
        for (int o = 8; o > 0; o >>= 1)
            s += __shfl_xor_sync(0x0000ffffu, s, o, 16);
        aw_s[w * 16 + lane] = ev / s;
    }
    __syncthreads();

    {
        const int TLS[4]    = {2048, 1024, 512, 256};
        const int STARTS[4] = {0, 2048, 3072, 3584};
        int pair = tid >> 1, half = tid & 1;
        int h2 = pair >> 4, lp = pair & 15, l = lp >> 2;
        int Tl = TLS[l], st = STARTS[l];
        float ref = rp[n * Ll + l];
        float off = g_off[n * HLP + pair];
        float aw = aw_s[pair];
        float x = ref * (float)Tl + off - 0.5f;
        float xf = floorf(x);
        float w1 = x - xf, w0 = 1.0f - w1;
        int i0 = (int)xf, i1 = i0 + 1;
        float wa0 = aw * w0 * ((i0 >= 0 && i0 < Tl) ? 1.f : 0.f);
        float wa1 = aw * w1 * ((i1 >= 0 && i1 < Tl) ? 1.f : 0.f);
        int c0i = min(max(i0, 0), Tl - 1);
        int c1i = min(max(i1, 0), Tl - 1);
        size_t base0 = ((size_t)(b * T_TOTAL + st + c0i)) * Dm + h2 * HD + half * 16;
        size_t base1 = ((size_t)(b * T_TOTAL + st + c1i)) * Dm + h2 * HD + half * 16;
#pragma unroll
        for (int q4 = 0; q4 < 4; q4++) {
            float4 v0 = *(const float4*)&g_value[base0 + q4 * 4];
            float4 v1 = *(const float4*)&g_value[base1 + q4 * 4];
            float fx[4];
            fx[0] = wa0 * v0.x + wa1 * v1.x;
            fx[1] = wa0 * v0.y + wa1 * v1.y;
            fx[2] = wa0 * v0.z + wa1 * v1.z;
            fx[3] = wa0 * v0.w + wa1 * v1.w;
            __half hh[4], ll[4];
#pragma unroll
            for (int i = 0; i < 4; i++) fp16_split(fx[i], hh[i], ll[i]);
            int d = half * 16 + q4 * 4;
            *(uint2*)&sAh3[pair * A3STR + d] = *(uint2*)hh;
            *(uint2*)&sAl3[pair * A3STR + d] = *(uint2*)ll;
        }
    }
    __syncthreads();

    uint32_t aH = smem_u32(sAh3), aL = smem_u32(sAl3);
    uint32_t bF = smem_u32(sBf3);
    int wm = (w >> 1) * 32, wnl = (w & 1) * 32;
    float scoreacc[2][2] = {{0.f, 0.f}, {0.f, 0.f}};

#pragma unroll
    for (int pass = 0; pass < 4; pass++) {
        uint32_t boff2 = (uint32_t)(pass * 64 * A3STR * 2);
        float acc[32];
#pragma unroll
        for (int i = 0; i < 32; i++) acc[i] = 0.f;
        mma_chunk2<2, 2>(aH, aL, bF + boff2,
                         A3STR * 2, wm, wnl, lane, acc);
#pragma unroll
        for (int mt = 0; mt < 2; mt++)
#pragma unroll
            for (int nt = 0; nt < 4; nt++) {
                float* a4 = &acc[(mt * 4 + nt) * 4];
                int e0 = pass * 64 + wnl + nt * 8 + (lane & 3) * 2;
                scoreacc[mt][0] += tanha(a4[0] + add_s[e0]) * Wa_s[e0];
                scoreacc[mt][0] += tanha(a4[1] + add_s[e0 + 1]) * Wa_s[e0 + 1];
                scoreacc[mt][1] += tanha(a4[2] + add_s[e0]) * Wa_s[e0];
                scoreacc[mt][1] += tanha(a4[3] + add_s[e0 + 1]) * Wa_s[e0 + 1];
            }
    }

#pragma unroll
    for (int mt = 0; mt < 2; mt++) {
        float s0 = scoreacc[mt][0], s1 = scoreacc[mt][1];
        s0 += __shfl_xor_sync(0xffffffffu, s0, 1);
        s0 += __shfl_xor_sync(0xffffffffu, s0, 2);
        s1 += __shfl_xor_sync(0xffffffffu, s1, 1);
        s1 += __shfl_xor_sync(0xffffffffu, s1, 2);
        if ((lane & 3) == 0) {
            atomicAdd(&sc_s[wm + mt * 16 + (lane >> 2)], s0);
            atomicAdd(&sc_s[wm + mt * 16 + 8 + (lane >> 2)], s1);
        }
    }
    __syncthreads();

    if (lane < 16) {
        float v = sc_s[w * 16 + lane];
        float mx = v;
#pragma unroll
        for (int o = 8; o > 0; o >>= 1)
            mx = fmaxf(mx, __shfl_xor_sync(0x0000ffffu, mx, o, 16));
        float ev = __expf(v - mx);
        float s = ev;
#pragma unroll
        for (int o = 8; o > 0; o >>= 1)
            s += __shfl_xor_sync(0x0000ffffu, s, o, 16);
        sc_s[w * 16 + lane] = ev / s;
    }
    __syncwarp();

    {
        float accw = 0.f;
#pragma unroll
        for (int p = 0; p < 16; p++) {
            int r = (w * 16 + p) * A3STR + lane;
            accw += sc_s[w * 16 + p] *
                    (__half2float(sAh3[r]) + __half2float(sAl3[r]));
        }
        g_attnres[(size_t)n * Dm + w * HD + lane] = accw;
    }
}

// =====================================================================
// K4a/K4b: gates GEMMs (fp16 2-term)
// =====================================================================
template<int NCHUNK, bool ACCUM>
__device__ __forceinline__ void gates_core(
    const float* token, const float* query, const float* h0, int tid)
{
    extern __shared__ char smem[];
    uint32_t sb = smem_u32(smem);
    int w = tid >> 5, lane = tid & 31;
    int wm = (w >> 2) * 32, wn = (w & 3) * 32;
    int row0 = blockIdx.y * 64;
    int col0 = blockIdx.x * 128;

    float acc[32];
#pragma unroll
    for (int i = 0; i < 32; i++) acc[i] = 0.f;

    __half* sAh = (__half*)(smem + OFF_AH);
    __half* sAl = (__half*)(smem + OFF_AL);
    __half* sBf = (__half*)(smem + OFF_BF);

    const int segbase[3] = {0, 512, 768};
    for (int c = 0; c < NCHUNK; c++) {
        const float* src;
        int kcol;
        if (ACCUM) { src = g_attnres; kcol = 256 + c * 64; }
        else {
            int seg = c >> 2;
            src = (seg == 0) ? token : (seg == 1) ? query : h0;
            kcol = segbase[seg] + (c & 3) * 64;
        }
        int kkb = (c & 3) * 64;
        for (int g = tid; g < 512; g += 256) {
            int m = g >> 3, kg = g & 7;
            const float* s = src + (size_t)(row0 + m) * Dm + kkb + kg * 8;
            float4 v0 = *(const float4*)s;
            float4 v1 = *(const float4*)(s + 4);
            float xs[8] = {v0.x, v0.y, v0.z, v0.w, v1.x, v1.y, v1.z, v1.w};
            __half hh[8], ll[8];
#pragma unroll
            for (int i = 0; i < 8; i++) fp16_split(xs[i], hh[i], ll[i]);
            *(uint4*)&sAh[m * STR + kg * 8] = *(uint4*)hh;
            *(uint4*)&sAl[m * STR + kg * 8] = *(uint4*)ll;
        }
        for (int g = tid; g < 1024; g += 256) {
            int n = g >> 3, kg = g & 7;
            size_t gi = (size_t)(col0 + n) * 1024 + kcol + kg * 8;
            *(uint4*)&sBf[n * STR + kg * 8] = *(const uint4*)&g_Gf[gi];
        }
        __syncthreads();
        mma_chunk2<2, 4>(sb + OFF_AH, sb + OFF_AL, sb + OFF_BF,
                         STR * 2, wm, wn, lane, acc);
        __syncthreads();
    }

#pragma unroll
    for (int mt = 0; mt < 2; mt++)
#pragma unroll
        for (int nt = 0; nt < 4; nt++) {
            float* a4 = &acc[(mt * 4 + nt) * 4];
            int r = row0 + wm + mt * 16 + (lane >> 2);
            int cg = col0 + wn + nt * 8 + (lane & 3) * 2;
            float* p0 = &g_gates[(size_t)r * 1024 + cg];
            float* p1 = &g_gates[(size_t)(r + 8) * 1024 + cg];
            if (ACCUM) {
                float2 o0 = *(float2*)p0, o1 = *(float2*)p1;
                *(float2*)p0 = make_float2(o0.x + a4[0], o0.y + a4[1]);
                *(float2*)p1 = make_float2(o1.x + a4[2], o1.y + a4[3]);
            } else {
                *(float2*)p0 = make_float2(a4[0], a4[1]);
                *(float2*)p1 = make_float2(a4[2], a4[3]);
            }
        }
}

__global__ __launch_bounds__(256) void k_gates768(
    const float* __restrict__ token, const float* __restrict__ query,
    const float* __restrict__ h0)
{
    gates_core<12, false>(token, query, h0, threadIdx.x);
}
__global__ __launch_bounds__(256) void k_gates256()
{
    gates_core<4, true>(nullptr, nullptr, nullptr, threadIdx.x);
}

// =====================================================================
// K5: LSTM elementwise + output writes
// =====================================================================
__global__ __launch_bounds__(256) void k_lstm_ew(
    const float* __restrict__ c0, float* __restrict__ out, int write3)
{
    int n = blockIdx.x;
    int d = threadIdx.x;
    size_t g = (size_t)n * 1024;
    float gi = g_gates[g + d];
    float gf = g_gates[g + 256 + d];
    float gg = g_gates[g + 512 + d];
    float go = g_gates[g + 768 + d];
    float cprev = c0[(size_t)n * Dm + d];
    float cnew = sigm(gf) * cprev + sigm(gi) * tanh_fast(gg);
    float hnew = sigm(go) * tanh_fast(cnew);
    size_t idx = (size_t)n * Dm + d;
    out[idx] = hnew;
    if (write3) {
        out[(size_t)Nn * Dm + idx]     = hnew;
        out[(size_t)2 * Nn * Dm + idx] = cnew;
    }
}

// ---------------- streams/events (static init, outside capture) ----------
static cudaStream_t g_s1 = nullptr;
static cudaEvent_t g_e0 = nullptr, g_e_proj = nullptr, g_e_g768 = nullptr;
static bool g_streams_ok = false;
static struct StreamInit {
    StreamInit() {
        bool ok = true;
        ok &= (cudaStreamCreateWithFlags(&g_s1, cudaStreamNonBlocking) == cudaSuccess);
        ok &= (cudaEventCreateWithFlags(&g_e0, cudaEventDisableTiming) == cudaSuccess);
        ok &= (cudaEventCreateWithFlags(&g_e_proj, cudaEventDisableTiming) == cudaSuccess);
        ok &= (cudaEventCreateWithFlags(&g_e_g768, cudaEventDisableTiming) == cudaSuccess);
        g_streams_ok = ok;
    }
} g_stream_init;

// =====================================================================
// launch
// =====================================================================
extern "C" void kernel_launch(void* const* d_in, const int* in_sizes, int n_in,
                              void* d_out, int out_size)
{
    const float* token  = (const float*)d_in[0];
    const float* h0     = (const float*)d_in[1];
    const float* c0     = (const float*)d_in[2];
    const float* query  = (const float*)d_in[3];
    const float* rp     = (const float*)d_in[4];
    const float* ehs    = (const float*)d_in[5];
    const float* Wvalue = (const float*)d_in[8];
    const float* bvalue = (const float*)d_in[9];
    const float* Woff   = (const float*)d_in[10];
    const float* boff   = (const float*)d_in[11];
    const float* Waw    = (const float*)d_in[12];
    const float* baw    = (const float*)d_in[13];
    const float* Wctx   = (const float*)d_in[14];
    const float* bctx   = (const float*)d_in[15];
    const float* Whs    = (const float*)d_in[16];
    const float* bhs    = (const float*)d_in[17];
    const float* Walpha = (const float*)d_in[18];
    const float* Wih    = (const float*)d_in[20];
    const float* Whh    = (const float*)d_in[21];
    float* out = (float*)d_out;

    cudaFuncSetAttribute(k_value_mma,
                         cudaFuncAttributeMaxDynamicSharedMemorySize, V_SMEM);
    cudaFuncSetAttribute(k_proj_mma,
                         cudaFuncAttributeMaxDynamicSharedMemorySize, GEMM_SMEM);
    cudaFuncSetAttribute(k_sample_attn,
                         cudaFuncAttributeMaxDynamicSharedMemorySize, S3_SMEM);
    cudaFuncSetAttribute(k_gates768,
                         cudaFuncAttributeMaxDynamicSharedMemorySize, GEMM_SMEM);
    cudaFuncSetAttribute(k_gates256,
                         cudaFuncAttributeMaxDynamicSharedMemorySize, GEMM_SMEM);

    int write3 = (out_size >= 3 * Nn * Dm) ? 1 : 0;
    const int PREP_REST_BLOCKS = (1048576 + 8192 + 262144 + 255) / 256;  // 5152

    if (g_streams_ok) {
        k_prep_B<<<256, 256>>>(Wvalue);
        cudaEventRecord(g_e0, 0);
        cudaStreamWaitEvent(g_s1, g_e0, 0);
        k_prep_rest<<<PREP_REST_BLOCKS, 256, 0, g_s1>>>(Wih, Whh, Wctx, Woff, Waw, Whs);
        k_proj_mma<<<dim3(4, 50), 256, GEMM_SMEM, g_s1>>>(h0, query, boff, baw, bhs, bctx);
        cudaEventRecord(g_e_proj, g_s1);
        k_gates768<<<dim3(8, 50), 256, GEMM_SMEM, g_s1>>>(token, query, h0);
        cudaEventRecord(g_e_g768, g_s1);
        k_value_mma<<<1920, 256, V_SMEM>>>(ehs, bvalue);
        cudaStreamWaitEvent(0, g_e_proj, 0);
        k_sample_attn<<<Nn, 256, S3_SMEM>>>(rp, Walpha);
        cudaStreamWaitEvent(0, g_e_g768, 0);
        k_gates256<<<dim3(8, 50), 256, GEMM_SMEM>>>();
        k_lstm_ew<<<Nn, 256>>>(c0, out, write3);
    } else {
        k_prep_B<<<256, 256>>>(Wvalue);
        k_prep_rest<<<PREP_REST_BLOCKS, 256>>>(Wih, Whh, Wctx, Woff, Waw, Whs);
        k_proj_mma<<<dim3(4, 50), 256, GEMM_SMEM>>>(h0, query, boff, baw, bhs, bctx);
        k_gates768<<<dim3(8, 50), 256, GEMM_SMEM>>>(token, query, h0);
        k_value_mma<<<1920, 256, V_SMEM>>>(ehs, bvalue);
        k_sample_attn<<<Nn, 256, S3_SMEM>>>(rp, Walpha);
        k_gates256<<<dim3(8, 50), 256, GEMM_SMEM>>>();
        k_lstm_ew<<<Nn, 256>>>(c0, out, write3);
    }
}

// round 11
// speedup vs baseline: 1.5282x; 1.2237x over previous
#include <cuda_runtime.h>
#include <cuda_fp16.h>
#include <cstdint>

// ---------------- problem constants ----------------
#define Dm 256
#define Hh 8
#define HD 32
#define Ll 4
#define Pp 4
#define Bb 32
#define NQ 100
#define Nn (Bb*NQ)          // 3200
#define T_TOTAL 3840
#define LP 16
#define HLP 128

// ---------------- device scratch ----------------
__device__ float g_value[(size_t)Bb * T_TOTAL * Dm];   // ~126MB
__device__ float g_off[Nn * HLP];
__device__ float g_awl[Nn * HLP];
__device__ float g_hsproj[Nn * Dm];
__device__ float g_attnres[Nn * Dm];
__device__ float g_gates[Nn * 4 * Dm];
// weights: single fp16
__device__ __half g_Bf[Dm * Dm];        // W_value^T [n][k]
__device__ __half g_Gf[1024 * 1024];    // [Wih|Whh] [j][k]
__device__ __half g_Cf[256 * 32];       // Wctx^T [e][d]
__device__ __half g_Pf[512 * 512];      // proj B [n][k]

__device__ __forceinline__ float tanh_fast(float x) {
    float e = __expf(2.0f * x);
    return 1.0f - 2.0f / (e + 1.0f);
}
__device__ __forceinline__ float tanha(float x) {
    float y;
    asm("tanh.approx.f32 %0, %1;" : "=f"(y) : "f"(x));
    return y;
}
__device__ __forceinline__ float sigm(float x) {
    return 1.0f / (1.0f + __expf(-x));
}
__device__ __forceinline__ uint32_t smem_u32(const void* p) {
    uint32_t a;
    asm("{ .reg .u64 t; cvta.to.shared.u64 t, %1; cvt.u32.u64 %0, t; }"
        : "=r"(a) : "l"(p));
    return a;
}

// ---------------- mma.sync / ldmatrix (fp16) ----------------
__device__ __forceinline__ void ldm_x4(uint32_t* r, uint32_t addr) {
    asm volatile("ldmatrix.sync.aligned.m8n8.x4.shared.b16 {%0,%1,%2,%3}, [%4];"
        : "=r"(r[0]), "=r"(r[1]), "=r"(r[2]), "=r"(r[3]) : "r"(addr));
}
#define MMAH(d, a, b) \
    asm volatile("mma.sync.aligned.m16n8k16.row.col.f32.f16.f16.f32 " \
        "{%0,%1,%2,%3}, {%4,%5,%6,%7}, {%8,%9}, {%0,%1,%2,%3};" \
        : "+f"((d)[0]), "+f"((d)[1]), "+f"((d)[2]), "+f"((d)[3]) \
        : "r"((a)[0]), "r"((a)[1]), "r"((a)[2]), "r"((a)[3]), \
          "r"((b)[0]), "r"((b)[1]))

// single-term chunk: A x B, both fp16
template<int NT2, int KS>
__device__ __forceinline__ void mma_chunk1(
    uint32_t aF, uint32_t bF,
    uint32_t stride2, int wm, int wn, int lane, float* acc)
{
    int arow = lane & 15, acol8 = (lane >> 4) * 8;
    int brow = ((lane >> 4) & 1) * 8 + (lane & 7);
    int bcol8 = ((lane >> 3) & 1) * 8;
#pragma unroll
    for (int ks = 0; ks < KS; ks++) {
        uint32_t Af[2][4], B[NT2][4];
#pragma unroll
        for (int mt = 0; mt < 2; mt++) {
            uint32_t off = (uint32_t)(wm + mt * 16 + arow) * stride2
                         + (uint32_t)(ks * 16 + acol8) * 2;
            ldm_x4(Af[mt], aF + off);
        }
#pragma unroll
        for (int nt2 = 0; nt2 < NT2; nt2++) {
            uint32_t off = (uint32_t)(wn + nt2 * 16 + brow) * stride2
                         + (uint32_t)(ks * 16 + bcol8) * 2;
            ldm_x4(B[nt2], bF + off);
        }
#pragma unroll
        for (int mt = 0; mt < 2; mt++)
#pragma unroll
            for (int nt = 0; nt < 2 * NT2; nt++)
                MMAH(acc + (mt * 2 * NT2 + nt) * 4, Af[mt],
                     (&B[nt >> 1][(nt & 1) * 2]));
    }
}

#define STR 72
// generic GEMM smem: A 9216, B 18432
#define OFF_AF 0
#define OFF_BF 9216
#define GEMM_SMEM 27648
// value: A 9216, B 36864
#define V_AF 0
#define V_BF 9216
#define V_SMEM 46080

// =====================================================================
// K0a: prep W_value -> fp16 (transposed)
// =====================================================================
__global__ __launch_bounds__(256) void k_prep_B(const float* __restrict__ Wvalue)
{
    int idx = blockIdx.x * 256 + threadIdx.x;   // < 65536
    int n = idx >> 8, k = idx & 255;
    g_Bf[idx] = __float2half_rn(Wvalue[k * Dm + n]);
}

// =====================================================================
// K0b: prep remaining weights -> fp16
// =====================================================================
__global__ __launch_bounds__(256) void k_prep_rest(
    const float* __restrict__ Wih, const float* __restrict__ Whh,
    const float* __restrict__ Wctx,
    const float* __restrict__ Woff, const float* __restrict__ Waw,
    const float* __restrict__ Whs)
{
    int idx = blockIdx.x * 256 + threadIdx.x;
    if (idx < 1048576) {
        int j = idx >> 10, k = idx & 1023;
        float v = (k < 768) ? Wih[(size_t)j * 768 + k]
                            : Whh[(size_t)j * 256 + (k - 768)];
        g_Gf[idx] = __float2half_rn(v);
    } else if (idx < 1048576 + 8192) {
        int i = idx - 1048576;
        int e = i >> 5, k = i & 31;
        g_Cf[i] = __float2half_rn(Wctx[k * 256 + e]);
    } else if (idx < 1056768 + 262144) {
        int i = idx - 1056768;
        int n = i >> 9, k = i & 511;
        float v;
        if (n < 128)      v = Woff[k * 128 + n];
        else if (n < 256) v = Waw[k * 128 + (n - 128)];
        else              v = (k < 256) ? Whs[k * 256 + (n - 256)] : 0.f;
        g_Pf[i] = __float2half_rn(v);
    }
}

// =====================================================================
// K1: value GEMM (fp16 1-term). M=122880, N=256, K=256. grid 1920, BM=64
// =====================================================================
__global__ __launch_bounds__(256, 2) void k_value_mma(
    const float* __restrict__ A, const float* __restrict__ bias)
{
    extern __shared__ char smem[];
    uint32_t sb = smem_u32(smem);
    int tid = threadIdx.x;
    int w = tid >> 5, lane = tid & 31;
    int wm = (w >> 2) * 32, wn = (w & 3) * 64;
    int row0 = blockIdx.x * 64;

    float acc[64];
#pragma unroll
    for (int i = 0; i < 64; i++) acc[i] = 0.f;

    __half* sAf = (__half*)(smem + V_AF);
    __half* sBf = (__half*)(smem + V_BF);

    uint4 pfA[2];
    auto ldA = [&](int c) {
#pragma unroll
        for (int i = 0; i < 2; i++) {
            int g = tid + i * 256;
            int m = g >> 3, kg = g & 7;
            const float* s = A + (size_t)(row0 + m) * Dm + c * 64 + kg * 8;
            float4 v0 = *(const float4*)s;
            float4 v1 = *(const float4*)(s + 4);
            __half hh[8];
            hh[0] = __float2half_rn(v0.x); hh[1] = __float2half_rn(v0.y);
            hh[2] = __float2half_rn(v0.z); hh[3] = __float2half_rn(v0.w);
            hh[4] = __float2half_rn(v1.x); hh[5] = __float2half_rn(v1.y);
            hh[6] = __float2half_rn(v1.z); hh[7] = __float2half_rn(v1.w);
            pfA[i] = *(uint4*)hh;
        }
    };
    auto stsA = [&]() {
#pragma unroll
        for (int i = 0; i < 2; i++) {
            int g = tid + i * 256;
            int m = g >> 3, kg = g & 7;
            *(uint4*)&sAf[m * STR + kg * 8] = pfA[i];
        }
    };

    ldA(0);
    for (int c = 0; c < 4; c++) {
        stsA();
        for (int g = tid; g < 2048; g += 256) {
            int n = g >> 3, kg = g & 7;
            int gi = n * Dm + c * 64 + kg * 8;
            *(uint4*)&sBf[n * STR + kg * 8] = *(const uint4*)&g_Bf[gi];
        }
        __syncthreads();
        if (c < 3) ldA(c + 1);
        mma_chunk1<4, 4>(sb + V_AF, sb + V_BF, STR * 2, wm, wn, lane, acc);
        __syncthreads();
    }

#pragma unroll
    for (int mt = 0; mt < 2; mt++)
#pragma unroll
        for (int nt = 0; nt < 8; nt++) {
            float* a4 = &acc[(mt * 8 + nt) * 4];
            int r = row0 + wm + mt * 16 + (lane >> 2);
            int cg = wn + nt * 8 + (lane & 3) * 2;
            float b0 = __ldg(&bias[cg]), b1 = __ldg(&bias[cg + 1]);
            *(float2*)&g_value[(size_t)r * Dm + cg] =
                make_float2(a4[0] + b0, a4[1] + b1);
            *(float2*)&g_value[(size_t)(r + 8) * Dm + cg] =
                make_float2(a4[2] + b0, a4[3] + b1);
        }
}

// =====================================================================
// K2: proj GEMM. [h0|query](3200x512) @ g_P(512x512). grid (4,50)
// =====================================================================
__global__ __launch_bounds__(256) void k_proj_mma(
    const float* __restrict__ h0, const float* __restrict__ query,
    const float* __restrict__ boff, const float* __restrict__ baw,
    const float* __restrict__ bhs,  const float* __restrict__ bctx)
{
    extern __shared__ char smem[];
    uint32_t sb = smem_u32(smem);
    int tid = threadIdx.x;
    int w = tid >> 5, lane = tid & 31;
    int wm = (w >> 2) * 32, wn = (w & 3) * 32;
    int row0 = blockIdx.y * 64;
    int col0 = blockIdx.x * 128;

    float acc[32];
#pragma unroll
    for (int i = 0; i < 32; i++) acc[i] = 0.f;

    __half* sAf = (__half*)(smem + OFF_AF);
    __half* sBf = (__half*)(smem + OFF_BF);

    for (int c = 0; c < 8; c++) {
        const float* src = (c < 4) ? h0 : query;
        int kkb = (c & 3) * 64;
        for (int g = tid; g < 512; g += 256) {
            int m = g >> 3, kg = g & 7;
            const float* s = src + (size_t)(row0 + m) * Dm + kkb + kg * 8;
            float4 v0 = *(const float4*)s;
            float4 v1 = *(const float4*)(s + 4);
            __half hh[8];
            hh[0] = __float2half_rn(v0.x); hh[1] = __float2half_rn(v0.y);
            hh[2] = __float2half_rn(v0.z); hh[3] = __float2half_rn(v0.w);
            hh[4] = __float2half_rn(v1.x); hh[5] = __float2half_rn(v1.y);
            hh[6] = __float2half_rn(v1.z); hh[7] = __float2half_rn(v1.w);
            *(uint4*)&sAf[m * STR + kg * 8] = *(uint4*)hh;
        }
        for (int g = tid; g < 1024; g += 256) {
            int n = g >> 3, kg = g & 7;
            int gi = (col0 + n) * 512 + c * 64 + kg * 8;
            *(uint4*)&sBf[n * STR + kg * 8] = *(const uint4*)&g_Pf[gi];
        }
        __syncthreads();
        mma_chunk1<2, 4>(sb + OFF_AF, sb + OFF_BF, STR * 2, wm, wn, lane, acc);
        __syncthreads();
    }

    int bx = blockIdx.x;
#pragma unroll
    for (int mt = 0; mt < 2; mt++)
#pragma unroll
        for (int nt = 0; nt < 4; nt++) {
            float* a4 = &acc[(mt * 4 + nt) * 4];
            int r = row0 + wm + mt * 16 + (lane >> 2);
            int cl = wn + nt * 8 + (lane & 3) * 2;
            if (bx == 0) {
                float b0 = __ldg(&boff[cl]), b1 = __ldg(&boff[cl + 1]);
                *(float2*)&g_off[r * 128 + cl] = make_float2(a4[0] + b0, a4[1] + b1);
                *(float2*)&g_off[(r + 8) * 128 + cl] = make_float2(a4[2] + b0, a4[3] + b1);
            } else if (bx == 1) {
                float b0 = __ldg(&baw[cl]), b1 = __ldg(&baw[cl + 1]);
                *(float2*)&g_awl[r * 128 + cl] = make_float2(a4[0] + b0, a4[1] + b1);
                *(float2*)&g_awl[(r + 8) * 128 + cl] = make_float2(a4[2] + b0, a4[3] + b1);
            } else {
                int col = (bx - 2) * 128 + cl;
                float b0 = __ldg(&bhs[col]) + __ldg(&bctx[col]);
                float b1 = __ldg(&bhs[col + 1]) + __ldg(&bctx[col + 1]);
                *(float2*)&g_hsproj[r * 256 + col] = make_float2(a4[0] + b0, a4[1] + b1);
                *(float2*)&g_hsproj[(r + 8) * 256 + col] = make_float2(a4[2] + b0, a4[3] + b1);
            }
        }
}

// =====================================================================
// K3: sample + additive attention (fp16 1-term)
// =====================================================================
#define A3STR 40
#define S3_AF  0
#define S3_BF  10240
#define S3_ADD 30720
#define S3_WA  31744
#define S3_AW  32768
#define S3_SC  33280
#define S3_SMEM 33792

__global__ __launch_bounds__(256) void k_sample_attn(
    const float* __restrict__ rp,
    const float* __restrict__ Walpha)
{
    extern __shared__ char sm3[];
    __half* sAf3 = (__half*)(sm3 + S3_AF);
    __half* sBf3 = (__half*)(sm3 + S3_BF);
    float* add_s = (float*)(sm3 + S3_ADD);
    float* Wa_s  = (float*)(sm3 + S3_WA);
    float* aw_s  = (float*)(sm3 + S3_AW);
    float* sc_s  = (float*)(sm3 + S3_SC);

    int n = blockIdx.x;
    int tid = threadIdx.x;
    int w = tid >> 5, lane = tid & 31;
    int b = n / NQ;

    for (int g = tid; g < 1024; g += 256) {
        int r = g >> 2, kg = (g & 3) * 8;
        *(uint4*)&sBf3[r * A3STR + kg] = *(const uint4*)&g_Cf[r * 32 + kg];
    }
    if (tid < 128) { aw_s[tid] = g_awl[n * 128 + tid]; sc_s[tid] = 0.f; }
    add_s[tid] = g_hsproj[n * 256 + tid];
    Wa_s[tid] = Walpha[tid];
    __syncthreads();

    if (lane < 16) {
        float v = aw_s[w * 16 + lane];
        float mx = v;
#pragma unroll
        for (int o = 8; o > 0; o >>= 1)
            mx = fmaxf(mx, __shfl_xor_sync(0x0000ffffu, mx, o, 16));
        float ev = __expf(v - mx);
        float s = ev;
#pragma unroll
        for (int o = 8; o > 0; o >>= 1)
            s += __shfl_xor_sync(0x0000ffffu, s, o, 16);
        aw_s[w * 16 + lane] = ev / s;
    }
    __syncthreads();

    {
        const int TLS[4]    = {2048, 1024, 512, 256};
        const int STARTS[4] = {0, 2048, 3072, 3584};
        int pair = tid >> 1, half = tid & 1;
        int h2 = pair >> 4, lp = pair & 15, l = lp >> 2;
        int Tl = TLS[l], st = STARTS[l];
        float ref = rp[n * Ll + l];
        float off = g_off[n * HLP + pair];
        float aw = aw_s[pair];
        float x = ref * (float)Tl + off - 0.5f;
        float xf = floorf(x);
        float w1 = x - xf, w0 = 1.0f - w1;
        int i0 = (int)xf, i1 = i0 + 1;
        float wa0 = aw * w0 * ((i0 >= 0 && i0 < Tl) ? 1.f : 0.f);
        float wa1 = aw * w1 * ((i1 >= 0 && i1 < Tl) ? 1.f : 0.f);
        int c0i = min(max(i0, 0), Tl - 1);
        int c1i = min(max(i1, 0), Tl - 1);
        size_t base0 = ((size_t)(b * T_TOTAL + st + c0i)) * Dm + h2 * HD + half * 16;
        size_t base1 = ((size_t)(b * T_TOTAL + st + c1i)) * Dm + h2 * HD + half * 16;
#pragma unroll
        for (int q4 = 0; q4 < 4; q4++) {
            float4 v0 = *(const float4*)&g_value[base0 + q4 * 4];
            float4 v1 = *(const float4*)&g_value[base1 + q4 * 4];
            __half hh[4];
            hh[0] = __float2half_rn(wa0 * v0.x + wa1 * v1.x);
            hh[1] = __float2half_rn(wa0 * v0.y + wa1 * v1.y);
            hh[2] = __float2half_rn(wa0 * v0.z + wa1 * v1.z);
            hh[3] = __float2half_rn(wa0 * v0.w + wa1 * v1.w);
            int d = half * 16 + q4 * 4;
            *(uint2*)&sAf3[pair * A3STR + d] = *(uint2*)hh;
        }
    }
    __syncthreads();

    uint32_t aF = smem_u32(sAf3);
    uint32_t bF = smem_u32(sBf3);
    int wm = (w >> 1) * 32, wnl = (w & 1) * 32;
    float scoreacc[2][2] = {{0.f, 0.f}, {0.f, 0.f}};

#pragma unroll
    for (int pass = 0; pass < 4; pass++) {
        uint32_t boff2 = (uint32_t)(pass * 64 * A3STR * 2);
        float acc[32];
#pragma unroll
        for (int i = 0; i < 32; i++) acc[i] = 0.f;
        mma_chunk1<2, 2>(aF, bF + boff2, A3STR * 2, wm, wnl, lane, acc);
#pragma unroll
        for (int mt = 0; mt < 2; mt++)
#pragma unroll
            for (int nt = 0; nt < 4; nt++) {
                float* a4 = &acc[(mt * 4 + nt) * 4];
                int e0 = pass * 64 + wnl + nt * 8 + (lane & 3) * 2;
                scoreacc[mt][0] += tanha(a4[0] + add_s[e0]) * Wa_s[e0];
                scoreacc[mt][0] += tanha(a4[1] + add_s[e0 + 1]) * Wa_s[e0 + 1];
                scoreacc[mt][1] += tanha(a4[2] + add_s[e0]) * Wa_s[e0];
                scoreacc[mt][1] += tanha(a4[3] + add_s[e0 + 1]) * Wa_s[e0 + 1];
            }
    }

#pragma unroll
    for (int mt = 0; mt < 2; mt++) {
        float s0 = scoreacc[mt][0], s1 = scoreacc[mt][1];
        s0 += __shfl_xor_sync(0xffffffffu, s0, 1);
        s0 += __shfl_xor_sync(0xffffffffu, s0, 2);
        s1 += __shfl_xor_sync(0xffffffffu, s1, 1);
        s1 += __shfl_xor_sync(0xffffffffu, s1, 2);
        if ((lane & 3) == 0) {
            atomicAdd(&sc_s[wm + mt * 16 + (lane >> 2)], s0);
            atomicAdd(&sc_s[wm + mt * 16 + 8 + (lane >> 2)], s1);
        }
    }
    __syncthreads();

    if (lane < 16) {
        float v = sc_s[w * 16 + lane];
        float mx = v;
#pragma unroll
        for (int o = 8; o > 0; o >>= 1)
            mx = fmaxf(mx, __shfl_xor_sync(0x0000ffffu, mx, o, 16));
        float ev = __expf(v - mx);
        float s = ev;
#pragma unroll
        for (int o = 8; o > 0; o >>= 1)
            s += __shfl_xor_sync(0x0000ffffu, s, o, 16);
        sc_s[w * 16 + lane] = ev / s;
    }
    __syncwarp();

    {
        float accw = 0.f;
#pragma unroll
        for (int p = 0; p < 16; p++) {
            int r = (w * 16 + p) * A3STR + lane;
            accw += sc_s[w * 16 + p] * __half2float(sAf3[r]);
        }
        g_attnres[(size_t)n * Dm + w * HD + lane] = accw;
    }
}

// =====================================================================
// K4a/K4b: gates GEMMs (fp16 1-term)
// =====================================================================
template<int NCHUNK, bool ACCUM>
__device__ __forceinline__ void gates_core(
    const float* token, const float* query, const float* h0, int tid)
{
    extern __shared__ char smem[];
    uint32_t sb = smem_u32(smem);
    int w = tid >> 5, lane = tid & 31;
    int wm = (w >> 2) * 32, wn = (w & 3) * 32;
    int row0 = blockIdx.y * 64;
    int col0 = blockIdx.x * 128;

    float acc[32];
#pragma unroll
    for (int i = 0; i < 32; i++) acc[i] = 0.f;

    __half* sAf = (__half*)(smem + OFF_AF);
    __half* sBf = (__half*)(smem + OFF_BF);

    const int segbase[3] = {0, 512, 768};
    for (int c = 0; c < NCHUNK; c++) {
        const float* src;
        int kcol;
        if (ACCUM) { src = g_attnres; kcol = 256 + c * 64; }
        else {
            int seg = c >> 2;
            src = (seg == 0) ? token : (seg == 1) ? query : h0;
            kcol = segbase[seg] + (c & 3) * 64;
        }
        int kkb = (c & 3) * 64;
        for (int g = tid; g < 512; g += 256) {
            int m = g >> 3, kg = g & 7;
            const float* s = src + (size_t)(row0 + m) * Dm + kkb + kg * 8;
            float4 v0 = *(const float4*)s;
            float4 v1 = *(const float4*)(s + 4);
            __half hh[8];
            hh[0] = __float2half_rn(v0.x); hh[1] = __float2half_rn(v0.y);
            hh[2] = __float2half_rn(v0.z); hh[3] = __float2half_rn(v0.w);
            hh[4] = __float2half_rn(v1.x); hh[5] = __float2half_rn(v1.y);
            hh[6] = __float2half_rn(v1.z); hh[7] = __float2half_rn(v1.w);
            *(uint4*)&sAf[m * STR + kg * 8] = *(uint4*)hh;
        }
        for (int g = tid; g < 1024; g += 256) {
            int n = g >> 3, kg = g & 7;
            size_t gi = (size_t)(col0 + n) * 1024 + kcol + kg * 8;
            *(uint4*)&sBf[n * STR + kg * 8] = *(const uint4*)&g_Gf[gi];
        }
        __syncthreads();
        mma_chunk1<2, 4>(sb + OFF_AF, sb + OFF_BF, STR * 2, wm, wn, lane, acc);
        __syncthreads();
    }

#pragma unroll
    for (int mt = 0; mt < 2; mt++)
#pragma unroll
        for (int nt = 0; nt < 4; nt++) {
            float* a4 = &acc[(mt * 4 + nt) * 4];
            int r = row0 + wm + mt * 16 + (lane >> 2);
            int cg = col0 + wn + nt * 8 + (lane & 3) * 2;
            float* p0 = &g_gates[(size_t)r * 1024 + cg];
            float* p1 = &g_gates[(size_t)(r + 8) * 1024 + cg];
            if (ACCUM) {
                float2 o0 = *(float2*)p0, o1 = *(float2*)p1;
                *(float2*)p0 = make_float2(o0.x + a4[0], o0.y + a4[1]);
                *(float2*)p1 = make_float2(o1.x + a4[2], o1.y + a4[3]);
            } else {
                *(float2*)p0 = make_float2(a4[0], a4[1]);
                *(float2*)p1 = make_float2(a4[2], a4[3]);
            }
        }
}

__global__ __launch_bounds__(256) void k_gates768(
    const float* __restrict__ token, const float* __restrict__ query,
    const float* __restrict__ h0)
{
    gates_core<12, false>(token, query, h0, threadIdx.x);
}
__global__ __launch_bounds__(256) void k_gates256()
{
    gates_core<4, true>(nullptr, nullptr, nullptr, threadIdx.x);
}

// =====================================================================
// K5: LSTM elementwise + output writes
// =====================================================================
__global__ __launch_bounds__(256) void k_lstm_ew(
    const float* __restrict__ c0, float* __restrict__ out, int write3)
{
    int n = blockIdx.x;
    int d = threadIdx.x;
    size_t g = (size_t)n * 1024;
    float gi = g_gates[g + d];
    float gf = g_gates[g + 256 + d];
    float gg = g_gates[g + 512 + d];
    float go = g_gates[g + 768 + d];
    float cprev = c0[(size_t)n * Dm + d];
    float cnew = sigm(gf) * cprev + sigm(gi) * tanh_fast(gg);
    float hnew = sigm(go) * tanh_fast(cnew);
    size_t idx = (size_t)n * Dm + d;
    out[idx] = hnew;
    if (write3) {
        out[(size_t)Nn * Dm + idx]     = hnew;
        out[(size_t)2 * Nn * Dm + idx] = cnew;
    }
}

// ---------------- streams/events (static init, outside capture) ----------
static cudaStream_t g_s1 = nullptr;
static cudaEvent_t g_e0 = nullptr, g_e_proj = nullptr, g_e_g768 = nullptr;
static bool g_streams_ok = false;
static struct StreamInit {
    StreamInit() {
        bool ok = true;
        ok &= (cudaStreamCreateWithFlags(&g_s1, cudaStreamNonBlocking) == cudaSuccess);
        ok &= (cudaEventCreateWithFlags(&g_e0, cudaEventDisableTiming) == cudaSuccess);
        ok &= (cudaEventCreateWithFlags(&g_e_proj, cudaEventDisableTiming) == cudaSuccess);
        ok &= (cudaEventCreateWithFlags(&g_e_g768, cudaEventDisableTiming) == cudaSuccess);
        g_streams_ok = ok;
    }
} g_stream_init;

// =====================================================================
// launch
// =====================================================================
extern "C" void kernel_launch(void* const* d_in, const int* in_sizes, int n_in,
                              void* d_out, int out_size)
{
    const float* token  = (const float*)d_in[0];
    const float* h0     = (const float*)d_in[1];
    const float* c0     = (const float*)d_in[2];
    const float* query  = (const float*)d_in[3];
    const float* rp     = (const float*)d_in[4];
    const float* ehs    = (const float*)d_in[5];
    const float* Wvalue = (const float*)d_in[8];
    const float* bvalue = (const float*)d_in[9];
    const float* Woff   = (const float*)d_in[10];
    const float* boff   = (const float*)d_in[11];
    const float* Waw    = (const float*)d_in[12];
    const float* baw    = (const float*)d_in[13];
    const float* Wctx   = (const float*)d_in[14];
    const float* bctx   = (const float*)d_in[15];
    const float* Whs    = (const float*)d_in[16];
    const float* bhs    = (const float*)d_in[17];
    const float* Walpha = (const float*)d_in[18];
    const float* Wih    = (const float*)d_in[20];
    const float* Whh    = (const float*)d_in[21];
    float* out = (float*)d_out;

    cudaFuncSetAttribute(k_value_mma,
                         cudaFuncAttributeMaxDynamicSharedMemorySize, V_SMEM);
    cudaFuncSetAttribute(k_proj_mma,
                         cudaFuncAttributeMaxDynamicSharedMemorySize, GEMM_SMEM);
    cudaFuncSetAttribute(k_sample_attn,
                         cudaFuncAttributeMaxDynamicSharedMemorySize, S3_SMEM);
    cudaFuncSetAttribute(k_gates768,
                         cudaFuncAttributeMaxDynamicSharedMemorySize, GEMM_SMEM);
    cudaFuncSetAttribute(k_gates256,
                         cudaFuncAttributeMaxDynamicSharedMemorySize, GEMM_SMEM);

    int write3 = (out_size >= 3 * Nn * Dm) ? 1 : 0;
    const int PREP_REST_BLOCKS = (1048576 + 8192 + 262144 + 255) / 256;  // 5152

    if (g_streams_ok) {
        k_prep_B<<<256, 256>>>(Wvalue);
        cudaEventRecord(g_e0, 0);
        cudaStreamWaitEvent(g_s1, g_e0, 0);
        k_prep_rest<<<PREP_REST_BLOCKS, 256, 0, g_s1>>>(Wih, Whh, Wctx, Woff, Waw, Whs);
        k_proj_mma<<<dim3(4, 50), 256, GEMM_SMEM, g_s1>>>(h0, query, boff, baw, bhs, bctx);
        cudaEventRecord(g_e_proj, g_s1);
        k_gates768<<<dim3(8, 50), 256, GEMM_SMEM, g_s1>>>(token, query, h0);
        cudaEventRecord(g_e_g768, g_s1);
        k_value_mma<<<1920, 256, V_SMEM>>>(ehs, bvalue);
        cudaStreamWaitEvent(0, g_e_proj, 0);
        k_sample_attn<<<Nn, 256, S3_SMEM>>>(rp, Walpha);
        cudaStreamWaitEvent(0, g_e_g768, 0);
        k_gates256<<<dim3(8, 50), 256, GEMM_SMEM>>>();
        k_lstm_ew<<<Nn, 256>>>(c0, out, write3);
    } else {
        k_prep_B<<<256, 256>>>(Wvalue);
        k_prep_rest<<<PREP_REST_BLOCKS, 256>>>(Wih, Whh, Wctx, Woff, Waw, Whs);
        k_proj_mma<<<dim3(4, 50), 256, GEMM_SMEM>>>(h0, query, boff, baw, bhs, bctx);
        k_gates768<<<dim3(8, 50), 256, GEMM_SMEM>>>(token, query, h0);
        k_value_mma<<<1920, 256, V_SMEM>>>(ehs, bvalue);
        k_sample_attn<<<Nn, 256, S3_SMEM>>>(rp, Walpha);
        k_gates256<<<dim3(8, 50), 256, GEMM_SMEM>>>();
        k_lstm_ew<<<Nn, 256>>>(c0, out, write3);
    }
}